// round 5
// baseline (speedup 1.0000x reference)
#include <cuda_runtime.h>
#include <cuda_bf16.h>
#include <math.h>
#include <stdint.h>

// ---------------------------------------------------------------------------
// GatedGCN on GB300 — round 4
//   Key restructure: A@(x@W) = (A@x)@W  — SpMM moves BEFORE the GEMM.
//   Per layer: Y = A@feat (256-wide gather SpMM, epilogue writes bf16 hi/lo
//   split), then GEMM Y@[W|G] with W/G columns INTERLEAVED so the fused
//   epilogue computes sigmoid(g)*s (+relu) entirely in-register.
//   GEMM: portable mma.sync bf16, split-precision 3-term (virtual K=768).
// ---------------------------------------------------------------------------

#define MAXN 50000
#define MAXE 800000
#define D0 256
#define D1 256
#define D2 128

// ---------------- scratch (device globals) ----------------
__device__ __nv_bfloat16 g_Y1[(size_t)MAXN * 512];    // [N,512] = [Y1h | Y1l]
__device__ __nv_bfloat16 g_Y2[(size_t)MAXN * 512];    // [N,512] = [Y2h | Y2l]
__device__ float         g_h [(size_t)MAXN * 256];    // hidden, fp32
__device__ __nv_bfloat16 g_Bt1[(size_t)512 * 768];    // interleaved W1/G1 cols
__device__ __nv_bfloat16 g_Bt2[(size_t)256 * 768];    // interleaved W2/G2 cols
__device__ int   g_counts[MAXN];
__device__ int   g_rowptr[MAXN + 1];
__device__ int   g_cursor[MAXN];
__device__ int   g_ecol[MAXE];
__device__ float g_eval[MAXE];

// ---------------- PTX helpers ----------------
__device__ __forceinline__ uint32_t smem_u32(const void* p) {
    uint32_t a;
    asm("{ .reg .u64 t; cvta.to.shared.u64 t, %1; cvt.u32.u64 %0, t; }" : "=r"(a) : "l"(p));
    return a;
}
__device__ __forceinline__ uint32_t swz(uint32_t o) { return o ^ ((o >> 3) & 0x70); }

__device__ __forceinline__ void cp16(uint32_t dst, const void* src, int sz) {
    asm volatile("cp.async.cg.shared.global [%0], [%1], 16, %2;"
                 :: "r"(dst), "l"(src), "r"(sz));
}
__device__ __forceinline__ void cp_commit() { asm volatile("cp.async.commit_group;"); }
__device__ __forceinline__ void cp_wait1()  { asm volatile("cp.async.wait_group 1;"); }

__device__ __forceinline__ void ldm_x4(uint32_t& r0, uint32_t& r1, uint32_t& r2, uint32_t& r3,
                                       uint32_t addr) {
    asm volatile("ldmatrix.sync.aligned.m8n8.x4.shared.b16 {%0,%1,%2,%3}, [%4];"
                 : "=r"(r0), "=r"(r1), "=r"(r2), "=r"(r3) : "r"(addr));
}
__device__ __forceinline__ void mma_bf16(float& d0, float& d1, float& d2, float& d3,
                                         uint32_t a0, uint32_t a1, uint32_t a2, uint32_t a3,
                                         uint32_t b0, uint32_t b1) {
    asm volatile("mma.sync.aligned.m16n8k16.row.col.f32.bf16.bf16.f32 "
                 "{%0,%1,%2,%3}, {%4,%5,%6,%7}, {%8,%9}, {%0,%1,%2,%3};"
                 : "+f"(d0), "+f"(d1), "+f"(d2), "+f"(d3)
                 : "r"(a0), "r"(a1), "r"(a2), "r"(a3), "r"(b0), "r"(b1));
}

__device__ __forceinline__ void split_bf16(float v, __nv_bfloat16& h, __nv_bfloat16& l) {
    h = __float2bfloat16(v);
    l = __float2bfloat16(v - __bfloat162float(h));
}
__device__ __forceinline__ float sigmoidf_(float x) { return 1.0f / (1.0f + __expf(-x)); }

// ---------------------------------------------------------------------------
// Weight prep: W,G [256,Nw] fp32 -> Bt [2Nw][768] bf16.
// Row n: n even -> W[:, n/2], n odd -> G[:, n/2]  (column interleave).
// K' stacking: [hi(256) | lo(256) | hi(256)].
// ---------------------------------------------------------------------------
__global__ void conv_w(const float* __restrict__ W, const float* __restrict__ G,
                       __nv_bfloat16* __restrict__ Bt, int Nw)
{
    int idx = blockIdx.x * blockDim.x + threadIdx.x;
    int twoNw = 2 * Nw;
    if (idx >= twoNw * 256) return;
    int n = idx % twoNw;
    int k = idx / twoNw;
    int j = n >> 1;
    float w = (n & 1) ? G[(size_t)k * Nw + j] : W[(size_t)k * Nw + j];
    __nv_bfloat16 h, l;
    split_bf16(w, h, l);
    __nv_bfloat16* row = Bt + (size_t)n * 768;
    row[k]       = h;
    row[256 + k] = l;
    row[512 + k] = h;
}

// ---------------------------------------------------------------------------
// CSR build
// ---------------------------------------------------------------------------
__global__ void hist_kernel(const int* __restrict__ rows, int* __restrict__ counts, int E)
{
    int i = blockIdx.x * blockDim.x + threadIdx.x;
    if (i < E) atomicAdd(&counts[rows[i]], 1);
}

__global__ __launch_bounds__(1024)
void scan_kernel(const int* __restrict__ counts, int* __restrict__ rowptr,
                 int* __restrict__ cursor, int n)
{
    __shared__ int warpsums[32];
    __shared__ int s_running;
    const int tid  = threadIdx.x;
    const int lane = tid & 31;
    const int wid  = tid >> 5;
    if (tid == 0) s_running = 0;
    __syncthreads();

    for (int base = 0; base < n; base += 1024) {
        int i = base + tid;
        int v = (i < n) ? counts[i] : 0;
        int x = v;
#pragma unroll
        for (int d = 1; d < 32; d <<= 1) {
            int y = __shfl_up_sync(0xffffffffu, x, d);
            if (lane >= d) x += y;
        }
        if (lane == 31) warpsums[wid] = x;
        __syncthreads();
        if (wid == 0) {
            int w = warpsums[lane];
#pragma unroll
            for (int d = 1; d < 32; d <<= 1) {
                int y = __shfl_up_sync(0xffffffffu, w, d);
                if (lane >= d) w += y;
            }
            warpsums[lane] = w;
        }
        __syncthreads();
        int warpoff = (wid > 0) ? warpsums[wid - 1] : 0;
        int excl    = x - v + warpoff;
        int run     = s_running;
        if (i < n) { rowptr[i] = run + excl; cursor[i] = run + excl; }
        __syncthreads();
        if (tid == 1023) s_running = run + warpsums[31];
        __syncthreads();
    }
    if (threadIdx.x == 0) rowptr[n] = s_running;
}

__global__ void scatter_kernel(const int* __restrict__ rows, const int* __restrict__ cols,
                               const float* __restrict__ vals, int* __restrict__ cursor,
                               int* __restrict__ ecol, float* __restrict__ eval_, int E)
{
    int i = blockIdx.x * blockDim.x + threadIdx.x;
    if (i < E) {
        int pos = atomicAdd(&cursor[rows[i]], 1);
        ecol[pos]  = cols[i];
        eval_[pos] = vals[i];
    }
}

// ---------------------------------------------------------------------------
// SpMM: Y[r,:] = sum_e vals[e] * src[cols[e], :]   (src 256-wide fp32)
// One block (64 threads) per row; epilogue writes bf16 hi/lo split [N,512].
// ---------------------------------------------------------------------------
__global__ __launch_bounds__(64)
void spmm_split(const int* __restrict__ rowptr,
                const int* __restrict__ ecol,
                const float* __restrict__ eval_,
                const float* __restrict__ src,          // [N,256] fp32
                __nv_bfloat16* __restrict__ outs)       // [N,512] = [hi | lo]
{
    const int r = blockIdx.x;
    const int t = threadIdx.x;                          // 0..63
    const int s = rowptr[r];
    const int e = rowptr[r + 1];

    const float4* __restrict__ srcv = reinterpret_cast<const float4*>(src);

    float4 acc = make_float4(0.f, 0.f, 0.f, 0.f);

    int i = s;
    for (; i + 1 < e; i += 2) {
        int   c0 = ecol[i];     int   c1 = ecol[i + 1];
        float v0 = eval_[i];    float v1 = eval_[i + 1];
        float4 g0 = srcv[(size_t)c0 * 64 + t];
        float4 g1 = srcv[(size_t)c1 * 64 + t];
        acc.x = fmaf(v0, g0.x, acc.x); acc.y = fmaf(v0, g0.y, acc.y);
        acc.z = fmaf(v0, g0.z, acc.z); acc.w = fmaf(v0, g0.w, acc.w);
        acc.x = fmaf(v1, g1.x, acc.x); acc.y = fmaf(v1, g1.y, acc.y);
        acc.z = fmaf(v1, g1.z, acc.z); acc.w = fmaf(v1, g1.w, acc.w);
    }
    if (i < e) {
        int   c = ecol[i];
        float v = eval_[i];
        float4 g = srcv[(size_t)c * 64 + t];
        acc.x = fmaf(v, g.x, acc.x); acc.y = fmaf(v, g.y, acc.y);
        acc.z = fmaf(v, g.z, acc.z); acc.w = fmaf(v, g.w, acc.w);
    }

    float av[4] = {acc.x, acc.y, acc.z, acc.w};
    __nv_bfloat16 h[4], l[4];
#pragma unroll
    for (int j = 0; j < 4; j++) split_bf16(av[j], h[j], l[j]);
    __nv_bfloat16* base = outs + (size_t)r * 512 + t * 4;
    *reinterpret_cast<__nv_bfloat162*>(base)           = __halves2bfloat162(h[0], h[1]);
    *reinterpret_cast<__nv_bfloat162*>(base + 2)       = __halves2bfloat162(h[2], h[3]);
    *reinterpret_cast<__nv_bfloat162*>(base + 256)     = __halves2bfloat162(l[0], l[1]);
    *reinterpret_cast<__nv_bfloat162*>(base + 256 + 2) = __halves2bfloat162(l[2], l[3]);
}

// ---------------------------------------------------------------------------
// mma.sync GEMM with fused gating epilogue.
//   A2 [M,512] bf16 split, Bt [2Nw,768] bf16 interleaved, virtual K=768.
//   acc col pairs (even, odd) = (s_j, g_j); out[m, j] = sigmoid(g)*s (+relu).
// 128x128 CTA tile (=> 64 gated output cols per CTA), double-buffered cp.async.
// ---------------------------------------------------------------------------
#define CH_BYTES 16384
#define SM_A0 0
#define SM_B0 (2 * CH_BYTES)
#define SM_TOTAL (4 * CH_BYTES)
#define NCHUNK 12

template <bool RELU>
__global__ __launch_bounds__(256)
void gemm_gate(const __nv_bfloat16* __restrict__ A2,   // [M, 512]
               const __nv_bfloat16* __restrict__ Bt,   // [2Nw, 768]
               float* __restrict__ Cg,                 // [M, Nw] gated output
               int M, int OutW)
{
    extern __shared__ char smem[];
    const uint32_t sb = smem_u32(smem);
    const int tid  = threadIdx.x;
    const int wid  = tid >> 5;
    const int lane = tid & 31;
    const int wm   = wid & 3;
    const int wn   = wid >> 2;
    const int m0    = blockIdx.y * 128;
    const int nbase = blockIdx.x * 128;

    const char* Ab = (const char*)A2;
    const char* Bb = (const char*)Bt;

    auto load_chunk = [&](int kc, int st) {
        const uint32_t sA = sb + SM_A0 + st * CH_BYTES;
        const uint32_t sB = sb + SM_B0 + st * CH_BYTES;
        const int ak = (kc < 8) ? (kc & 3) : (kc - 4);  // hi,hi,lo chunk seq
        const size_t abyte = (size_t)ak * 128;
        const size_t bbyte = (size_t)kc * 128;
#pragma unroll
        for (int i = 0; i < 4; i++) {
            int g   = tid + i * 256;
            int row = g >> 3;
            int c   = (g & 7) * 16;
            int m   = m0 + row;
            int sz  = (m < M) ? 16 : 0;
            int mc  = (m < M) ? m : (M - 1);
            cp16(sA + swz((uint32_t)(row * 128 + c)),
                 Ab + (size_t)mc * 1024 + abyte + c, sz);
            cp16(sB + swz((uint32_t)(row * 128 + c)),
                 Bb + (size_t)(nbase + row) * 1536 + bbyte + c, 16);
        }
        cp_commit();
    };

    float acc[2][8][4];
#pragma unroll
    for (int i = 0; i < 2; i++)
#pragma unroll
        for (int j = 0; j < 8; j++)
#pragma unroll
            for (int q = 0; q < 4; q++) acc[i][j][q] = 0.f;

    load_chunk(0, 0);
    load_chunk(1, 1);

    const int a_row_in_tile = lane & 15;
    const int a_chunk_half  = lane >> 4;
    const int b_row_in_pair = lane & 7;
    const int b_chunk_half  = (lane >> 3) & 1;
    const int b_tile_sel    = lane >> 4;

    for (int kc = 0; kc < NCHUNK; kc++) {
        const int st = kc & 1;
        const uint32_t sA = sb + SM_A0 + st * CH_BYTES;
        const uint32_t sB = sb + SM_B0 + st * CH_BYTES;

        cp_wait1();
        __syncthreads();

#pragma unroll
        for (int ks = 0; ks < 4; ks++) {
            uint32_t a[2][4];
#pragma unroll
            for (int i = 0; i < 2; i++) {
                int row = wm * 32 + i * 16 + a_row_in_tile;
                uint32_t addr = sA + swz((uint32_t)(row * 128 + (ks * 2 + a_chunk_half) * 16));
                ldm_x4(a[i][0], a[i][1], a[i][2], a[i][3], addr);
            }
            uint32_t b[8][2];
#pragma unroll
            for (int jp = 0; jp < 4; jp++) {
                int row = wn * 64 + (jp * 2 + b_tile_sel) * 8 + b_row_in_pair;
                uint32_t addr = sB + swz((uint32_t)(row * 128 + (ks * 2 + b_chunk_half) * 16));
                uint32_t r0, r1, r2, r3;
                ldm_x4(r0, r1, r2, r3, addr);
                b[jp * 2 + 0][0] = r0; b[jp * 2 + 0][1] = r1;
                b[jp * 2 + 1][0] = r2; b[jp * 2 + 1][1] = r3;
            }
#pragma unroll
            for (int i = 0; i < 2; i++)
#pragma unroll
                for (int j = 0; j < 8; j++)
                    mma_bf16(acc[i][j][0], acc[i][j][1], acc[i][j][2], acc[i][j][3],
                             a[i][0], a[i][1], a[i][2], a[i][3],
                             b[j][0], b[j][1]);
        }

        __syncthreads();
        if (kc + 2 < NCHUNK) load_chunk(kc + 2, st);
        else cp_commit();
    }

    // ---- fused gating epilogue ----
    const int qrow = lane >> 2;
    const int qcol = (lane & 3) * 2;   // always even -> (s, g) pair
#pragma unroll
    for (int i = 0; i < 2; i++) {
        int mA = m0 + wm * 32 + i * 16 + qrow;
        int mB = mA + 8;
#pragma unroll
        for (int j = 0; j < 8; j++) {
            int col = nbase + wn * 64 + j * 8 + qcol;
            int p   = col >> 1;
            float vA = sigmoidf_(acc[i][j][1]) * acc[i][j][0];
            float vB = sigmoidf_(acc[i][j][3]) * acc[i][j][2];
            if (RELU) { vA = fmaxf(vA, 0.f); vB = fmaxf(vB, 0.f); }
            if (mA < M) Cg[(size_t)mA * OutW + p] = vA;
            if (mB < M) Cg[(size_t)mB * OutW + p] = vB;
        }
    }
}

// ---------------------------------------------------------------------------
// kernel_launch — inputs: x, rows, cols, vals, W1, G1, W2, G2
// ---------------------------------------------------------------------------
extern "C" void kernel_launch(void* const* d_in, const int* in_sizes, int n_in,
                              void* d_out, int out_size)
{
    const float* x    = (const float*)d_in[0];
    const int*   rows = (const int*)  d_in[1];
    const int*   cols = (const int*)  d_in[2];
    const float* vals = (const float*)d_in[3];
    const float* W1   = (const float*)d_in[4];
    const float* G1   = (const float*)d_in[5];
    const float* W2   = (const float*)d_in[6];
    const float* G2   = (const float*)d_in[7];
    float* out = (float*)d_out;

    const int N = in_sizes[0] / D0;
    const int E = in_sizes[1];

    __nv_bfloat16 *Y1, *Y2, *Bt1, *Bt2;
    float *h, *evalp;
    int *counts, *rowptr, *cursor, *ecol;
    cudaGetSymbolAddress((void**)&Y1,     g_Y1);
    cudaGetSymbolAddress((void**)&Y2,     g_Y2);
    cudaGetSymbolAddress((void**)&h,      g_h);
    cudaGetSymbolAddress((void**)&Bt1,    g_Bt1);
    cudaGetSymbolAddress((void**)&Bt2,    g_Bt2);
    cudaGetSymbolAddress((void**)&counts, g_counts);
    cudaGetSymbolAddress((void**)&rowptr, g_rowptr);
    cudaGetSymbolAddress((void**)&cursor, g_cursor);
    cudaGetSymbolAddress((void**)&ecol,   g_ecol);
    cudaGetSymbolAddress((void**)&evalp,  g_eval);

    cudaFuncSetAttribute(gemm_gate<true>,  cudaFuncAttributeMaxDynamicSharedMemorySize, SM_TOTAL);
    cudaFuncSetAttribute(gemm_gate<false>, cudaFuncAttributeMaxDynamicSharedMemorySize, SM_TOTAL);

    const int mtiles  = (N + 127) / 128;
    const int eblocks = (E + 255) / 256;

    // ---- weight prep + CSR build ----
    conv_w<<<(2 * D1 * 256 + 255) / 256, 256>>>(W1, G1, Bt1, D1);
    conv_w<<<(2 * D2 * 256 + 255) / 256, 256>>>(W2, G2, Bt2, D2);
    cudaMemsetAsync(counts, 0, (size_t)N * sizeof(int));
    hist_kernel<<<eblocks, 256>>>(rows, counts, E);
    scan_kernel<<<1, 1024>>>(counts, rowptr, cursor, N);
    scatter_kernel<<<eblocks, 256>>>(rows, cols, vals, cursor, ecol, evalp, E);

    // ---- layer 1: Y1 = A@x ; h = relu(sigmoid(Y1@G1) * (Y1@W1)) ----
    spmm_split<<<N, 64>>>(rowptr, ecol, evalp, x, Y1);
    gemm_gate<true><<<dim3(4, mtiles), 256, SM_TOTAL>>>(Y1, Bt1, h, N, D1);

    // ---- layer 2: Y2 = A@h ; out = sigmoid(Y2@G2) * (Y2@W2) ----
    spmm_split<<<N, 64>>>(rowptr, ecol, evalp, h, Y2);
    gemm_gate<false><<<dim3(2, mtiles), 256, SM_TOTAL>>>(Y2, Bt2, out, N, D2);
}

// round 6
// speedup vs baseline: 1.5904x; 1.5904x over previous
#include <cuda_runtime.h>
#include <cuda_bf16.h>
#include <math.h>
#include <stdint.h>

// ---------------------------------------------------------------------------
// GatedGCN on GB300 — round 6
//   Structure (round 5): per layer Y = A@feat (256-wide SpMM, bf16 hi/lo
//   split epilogue) then fused GEMM Y@[W|G] with in-register sigmoid gating.
//   Fixes vs round 5: multi-block scan (was 64us single-block), SpMM with
//   4 rows/block x 64 threads and unroll-4 edge loop (MLP 2 -> 4+).
// ---------------------------------------------------------------------------

#define MAXN 50000
#define MAXE 800000
#define D0 256
#define D1 256
#define D2 128
#define SCAN_B 1024
#define MAXSB ((MAXN + SCAN_B - 1) / SCAN_B)

// ---------------- scratch (device globals) ----------------
__device__ __nv_bfloat16 g_Y1[(size_t)MAXN * 512];    // [N,512] = [Y1h | Y1l]
__device__ __nv_bfloat16 g_Y2[(size_t)MAXN * 512];    // [N,512] = [Y2h | Y2l]
__device__ float         g_h [(size_t)MAXN * 256];    // hidden, fp32
__device__ __nv_bfloat16 g_Bt1[(size_t)512 * 768];    // interleaved W1/G1 cols
__device__ __nv_bfloat16 g_Bt2[(size_t)256 * 768];    // interleaved W2/G2 cols
__device__ int   g_counts[MAXN];
__device__ int   g_rowptr[MAXN + 1];
__device__ int   g_cursor[MAXN];
__device__ int   g_ecol[MAXE];
__device__ float g_eval[MAXE];
__device__ int   g_bsum[MAXSB + 1];
__device__ int   g_boff[MAXSB + 1];

// ---------------- PTX helpers ----------------
__device__ __forceinline__ uint32_t smem_u32(const void* p) {
    uint32_t a;
    asm("{ .reg .u64 t; cvta.to.shared.u64 t, %1; cvt.u32.u64 %0, t; }" : "=r"(a) : "l"(p));
    return a;
}
__device__ __forceinline__ uint32_t swz(uint32_t o) { return o ^ ((o >> 3) & 0x70); }

__device__ __forceinline__ void cp16(uint32_t dst, const void* src, int sz) {
    asm volatile("cp.async.cg.shared.global [%0], [%1], 16, %2;"
                 :: "r"(dst), "l"(src), "r"(sz));
}
__device__ __forceinline__ void cp_commit() { asm volatile("cp.async.commit_group;"); }
__device__ __forceinline__ void cp_wait1()  { asm volatile("cp.async.wait_group 1;"); }

__device__ __forceinline__ void ldm_x4(uint32_t& r0, uint32_t& r1, uint32_t& r2, uint32_t& r3,
                                       uint32_t addr) {
    asm volatile("ldmatrix.sync.aligned.m8n8.x4.shared.b16 {%0,%1,%2,%3}, [%4];"
                 : "=r"(r0), "=r"(r1), "=r"(r2), "=r"(r3) : "r"(addr));
}
__device__ __forceinline__ void mma_bf16(float& d0, float& d1, float& d2, float& d3,
                                         uint32_t a0, uint32_t a1, uint32_t a2, uint32_t a3,
                                         uint32_t b0, uint32_t b1) {
    asm volatile("mma.sync.aligned.m16n8k16.row.col.f32.bf16.bf16.f32 "
                 "{%0,%1,%2,%3}, {%4,%5,%6,%7}, {%8,%9}, {%0,%1,%2,%3};"
                 : "+f"(d0), "+f"(d1), "+f"(d2), "+f"(d3)
                 : "r"(a0), "r"(a1), "r"(a2), "r"(a3), "r"(b0), "r"(b1));
}

__device__ __forceinline__ void split_bf16(float v, __nv_bfloat16& h, __nv_bfloat16& l) {
    h = __float2bfloat16(v);
    l = __float2bfloat16(v - __bfloat162float(h));
}
__device__ __forceinline__ float sigmoidf_(float x) { return 1.0f / (1.0f + __expf(-x)); }

// ---------------------------------------------------------------------------
// Weight prep: W,G [256,Nw] fp32 -> Bt [2Nw][768] bf16.
// Row n: n even -> W[:, n/2], n odd -> G[:, n/2].  K' = [hi | lo | hi].
// ---------------------------------------------------------------------------
__global__ void conv_w(const float* __restrict__ W, const float* __restrict__ G,
                       __nv_bfloat16* __restrict__ Bt, int Nw)
{
    int idx = blockIdx.x * blockDim.x + threadIdx.x;
    int twoNw = 2 * Nw;
    if (idx >= twoNw * 256) return;
    int n = idx % twoNw;
    int k = idx / twoNw;
    int j = n >> 1;
    float w = (n & 1) ? G[(size_t)k * Nw + j] : W[(size_t)k * Nw + j];
    __nv_bfloat16 h, l;
    split_bf16(w, h, l);
    __nv_bfloat16* row = Bt + (size_t)n * 768;
    row[k]       = h;
    row[256 + k] = l;
    row[512 + k] = h;
}

// ---------------------------------------------------------------------------
// CSR build: hist -> (block reduce, tiny serial scan, block scan) -> scatter
// ---------------------------------------------------------------------------
__global__ void hist_kernel(const int* __restrict__ rows, int* __restrict__ counts, int E)
{
    int i = blockIdx.x * blockDim.x + threadIdx.x;
    if (i < E) atomicAdd(&counts[rows[i]], 1);
}

__global__ __launch_bounds__(SCAN_B)
void scan_blocksum(const int* __restrict__ counts, int* __restrict__ bsum, int n)
{
    __shared__ int ws[32];
    const int tid  = threadIdx.x;
    const int lane = tid & 31;
    const int wid  = tid >> 5;
    int i = blockIdx.x * SCAN_B + tid;
    int v = (i < n) ? counts[i] : 0;
#pragma unroll
    for (int d = 16; d > 0; d >>= 1) v += __shfl_down_sync(0xffffffffu, v, d);
    if (lane == 0) ws[wid] = v;
    __syncthreads();
    if (wid == 0) {
        int w = ws[lane];
#pragma unroll
        for (int d = 16; d > 0; d >>= 1) w += __shfl_down_sync(0xffffffffu, w, d);
        if (lane == 0) bsum[blockIdx.x] = w;
    }
}

__global__ void scan_offsets(const int* __restrict__ bsum, int* __restrict__ boff,
                             int* __restrict__ rowptr, int nb, int n)
{
    if (threadIdx.x == 0) {
        int run = 0;
        for (int b = 0; b < nb; b++) { boff[b] = run; run += bsum[b]; }
        rowptr[n] = run;
    }
}

__global__ __launch_bounds__(SCAN_B)
void scan_final(const int* __restrict__ counts, const int* __restrict__ boff,
                int* __restrict__ rowptr, int* __restrict__ cursor, int n)
{
    __shared__ int ws[32];
    const int tid  = threadIdx.x;
    const int lane = tid & 31;
    const int wid  = tid >> 5;
    int i = blockIdx.x * SCAN_B + tid;
    int v = (i < n) ? counts[i] : 0;
    int x = v;
#pragma unroll
    for (int d = 1; d < 32; d <<= 1) {
        int y = __shfl_up_sync(0xffffffffu, x, d);
        if (lane >= d) x += y;
    }
    if (lane == 31) ws[wid] = x;
    __syncthreads();
    if (wid == 0) {
        int w = ws[lane];
#pragma unroll
        for (int d = 1; d < 32; d <<= 1) {
            int y = __shfl_up_sync(0xffffffffu, w, d);
            if (lane >= d) w += y;
        }
        ws[lane] = w;
    }
    __syncthreads();
    int excl = x - v + ((wid > 0) ? ws[wid - 1] : 0) + boff[blockIdx.x];
    if (i < n) { rowptr[i] = excl; cursor[i] = excl; }
}

__global__ void scatter_kernel(const int* __restrict__ rows, const int* __restrict__ cols,
                               const float* __restrict__ vals, int* __restrict__ cursor,
                               int* __restrict__ ecol, float* __restrict__ eval_, int E)
{
    int i = blockIdx.x * blockDim.x + threadIdx.x;
    if (i < E) {
        int pos = atomicAdd(&cursor[rows[i]], 1);
        ecol[pos]  = cols[i];
        eval_[pos] = vals[i];
    }
}

// ---------------------------------------------------------------------------
// SpMM: Y[r,:] = sum_e vals[e] * src[cols[e], :]  (src [N,256] fp32)
// 4 rows per 256-thread block (64 threads/row), unroll-4 edge loop.
// Epilogue writes bf16 hi/lo split [N,512].
// ---------------------------------------------------------------------------
__global__ __launch_bounds__(256)
void spmm_split(const int* __restrict__ rowptr,
                const int* __restrict__ ecol,
                const float* __restrict__ eval_,
                const float* __restrict__ src,          // [N,256] fp32
                __nv_bfloat16* __restrict__ outs,       // [N,512] = [hi | lo]
                int N)
{
    const int g = threadIdx.x >> 6;                     // row group 0..3
    const int t = threadIdx.x & 63;                     // feature float4 idx
    const int r = blockIdx.x * 4 + g;
    if (r >= N) return;

    const int s = rowptr[r];
    const int e = rowptr[r + 1];

    const float4* __restrict__ srcv = reinterpret_cast<const float4*>(src);

    float4 acc = make_float4(0.f, 0.f, 0.f, 0.f);

    int i = s;
    for (; i + 3 < e; i += 4) {
        int   c0 = ecol[i];     int   c1 = ecol[i + 1];
        int   c2 = ecol[i + 2]; int   c3 = ecol[i + 3];
        float v0 = eval_[i];    float v1 = eval_[i + 1];
        float v2 = eval_[i + 2];float v3 = eval_[i + 3];
        float4 g0 = srcv[(size_t)c0 * 64 + t];
        float4 g1 = srcv[(size_t)c1 * 64 + t];
        float4 g2 = srcv[(size_t)c2 * 64 + t];
        float4 g3 = srcv[(size_t)c3 * 64 + t];
        acc.x = fmaf(v0, g0.x, acc.x); acc.y = fmaf(v0, g0.y, acc.y);
        acc.z = fmaf(v0, g0.z, acc.z); acc.w = fmaf(v0, g0.w, acc.w);
        acc.x = fmaf(v1, g1.x, acc.x); acc.y = fmaf(v1, g1.y, acc.y);
        acc.z = fmaf(v1, g1.z, acc.z); acc.w = fmaf(v1, g1.w, acc.w);
        acc.x = fmaf(v2, g2.x, acc.x); acc.y = fmaf(v2, g2.y, acc.y);
        acc.z = fmaf(v2, g2.z, acc.z); acc.w = fmaf(v2, g2.w, acc.w);
        acc.x = fmaf(v3, g3.x, acc.x); acc.y = fmaf(v3, g3.y, acc.y);
        acc.z = fmaf(v3, g3.z, acc.z); acc.w = fmaf(v3, g3.w, acc.w);
    }
    for (; i < e; i++) {
        int   c = ecol[i];
        float v = eval_[i];
        float4 gg = srcv[(size_t)c * 64 + t];
        acc.x = fmaf(v, gg.x, acc.x); acc.y = fmaf(v, gg.y, acc.y);
        acc.z = fmaf(v, gg.z, acc.z); acc.w = fmaf(v, gg.w, acc.w);
    }

    float av[4] = {acc.x, acc.y, acc.z, acc.w};
    __nv_bfloat16 h[4], l[4];
#pragma unroll
    for (int j = 0; j < 4; j++) split_bf16(av[j], h[j], l[j]);
    __nv_bfloat16* base = outs + (size_t)r * 512 + t * 4;
    *reinterpret_cast<__nv_bfloat162*>(base)           = __halves2bfloat162(h[0], h[1]);
    *reinterpret_cast<__nv_bfloat162*>(base + 2)       = __halves2bfloat162(h[2], h[3]);
    *reinterpret_cast<__nv_bfloat162*>(base + 256)     = __halves2bfloat162(l[0], l[1]);
    *reinterpret_cast<__nv_bfloat162*>(base + 256 + 2) = __halves2bfloat162(l[2], l[3]);
}

// ---------------------------------------------------------------------------
// mma.sync GEMM with fused gating epilogue (unchanged from round 5).
// ---------------------------------------------------------------------------
#define CH_BYTES 16384
#define SM_A0 0
#define SM_B0 (2 * CH_BYTES)
#define SM_TOTAL (4 * CH_BYTES)
#define NCHUNK 12

template <bool RELU>
__global__ __launch_bounds__(256)
void gemm_gate(const __nv_bfloat16* __restrict__ A2,   // [M, 512]
               const __nv_bfloat16* __restrict__ Bt,   // [2Nw, 768]
               float* __restrict__ Cg,                 // [M, Nw] gated output
               int M, int OutW)
{
    extern __shared__ char smem[];
    const uint32_t sb = smem_u32(smem);
    const int tid  = threadIdx.x;
    const int wid  = tid >> 5;
    const int lane = tid & 31;
    const int wm   = wid & 3;
    const int wn   = wid >> 2;
    const int m0    = blockIdx.y * 128;
    const int nbase = blockIdx.x * 128;

    const char* Ab = (const char*)A2;
    const char* Bb = (const char*)Bt;

    auto load_chunk = [&](int kc, int st) {
        const uint32_t sA = sb + SM_A0 + st * CH_BYTES;
        const uint32_t sB = sb + SM_B0 + st * CH_BYTES;
        const int ak = (kc < 8) ? (kc & 3) : (kc - 4);  // Ah,Ah,Al sequence
        const size_t abyte = (size_t)ak * 128;
        const size_t bbyte = (size_t)kc * 128;
#pragma unroll
        for (int i = 0; i < 4; i++) {
            int g   = tid + i * 256;
            int row = g >> 3;
            int c   = (g & 7) * 16;
            int m   = m0 + row;
            int sz  = (m < M) ? 16 : 0;
            int mc  = (m < M) ? m : (M - 1);
            cp16(sA + swz((uint32_t)(row * 128 + c)),
                 Ab + (size_t)mc * 1024 + abyte + c, sz);
            cp16(sB + swz((uint32_t)(row * 128 + c)),
                 Bb + (size_t)(nbase + row) * 1536 + bbyte + c, 16);
        }
        cp_commit();
    };

    float acc[2][8][4];
#pragma unroll
    for (int i = 0; i < 2; i++)
#pragma unroll
        for (int j = 0; j < 8; j++)
#pragma unroll
            for (int q = 0; q < 4; q++) acc[i][j][q] = 0.f;

    load_chunk(0, 0);
    load_chunk(1, 1);

    const int a_row_in_tile = lane & 15;
    const int a_chunk_half  = lane >> 4;
    const int b_row_in_pair = lane & 7;
    const int b_chunk_half  = (lane >> 3) & 1;
    const int b_tile_sel    = lane >> 4;

    for (int kc = 0; kc < NCHUNK; kc++) {
        const int st = kc & 1;
        const uint32_t sA = sb + SM_A0 + st * CH_BYTES;
        const uint32_t sB = sb + SM_B0 + st * CH_BYTES;

        cp_wait1();
        __syncthreads();

#pragma unroll
        for (int ks = 0; ks < 4; ks++) {
            uint32_t a[2][4];
#pragma unroll
            for (int i = 0; i < 2; i++) {
                int row = wm * 32 + i * 16 + a_row_in_tile;
                uint32_t addr = sA + swz((uint32_t)(row * 128 + (ks * 2 + a_chunk_half) * 16));
                ldm_x4(a[i][0], a[i][1], a[i][2], a[i][3], addr);
            }
            uint32_t b[8][2];
#pragma unroll
            for (int jp = 0; jp < 4; jp++) {
                int row = wn * 64 + (jp * 2 + b_tile_sel) * 8 + b_row_in_pair;
                uint32_t addr = sB + swz((uint32_t)(row * 128 + (ks * 2 + b_chunk_half) * 16));
                uint32_t r0, r1, r2, r3;
                ldm_x4(r0, r1, r2, r3, addr);
                b[jp * 2 + 0][0] = r0; b[jp * 2 + 0][1] = r1;
                b[jp * 2 + 1][0] = r2; b[jp * 2 + 1][1] = r3;
            }
#pragma unroll
            for (int i = 0; i < 2; i++)
#pragma unroll
                for (int j = 0; j < 8; j++)
                    mma_bf16(acc[i][j][0], acc[i][j][1], acc[i][j][2], acc[i][j][3],
                             a[i][0], a[i][1], a[i][2], a[i][3],
                             b[j][0], b[j][1]);
        }

        __syncthreads();
        if (kc + 2 < NCHUNK) load_chunk(kc + 2, st);
        else cp_commit();
    }

    // ---- fused gating epilogue ----
    const int qrow = lane >> 2;
    const int qcol = (lane & 3) * 2;   // even -> (s, g) pair
#pragma unroll
    for (int i = 0; i < 2; i++) {
        int mA = m0 + wm * 32 + i * 16 + qrow;
        int mB = mA + 8;
#pragma unroll
        for (int j = 0; j < 8; j++) {
            int col = nbase + wn * 64 + j * 8 + qcol;
            int p   = col >> 1;
            float vA = sigmoidf_(acc[i][j][1]) * acc[i][j][0];
            float vB = sigmoidf_(acc[i][j][3]) * acc[i][j][2];
            if (RELU) { vA = fmaxf(vA, 0.f); vB = fmaxf(vB, 0.f); }
            if (mA < M) Cg[(size_t)mA * OutW + p] = vA;
            if (mB < M) Cg[(size_t)mB * OutW + p] = vB;
        }
    }
}

// ---------------------------------------------------------------------------
// kernel_launch — inputs: x, rows, cols, vals, W1, G1, W2, G2
// ---------------------------------------------------------------------------
extern "C" void kernel_launch(void* const* d_in, const int* in_sizes, int n_in,
                              void* d_out, int out_size)
{
    const float* x    = (const float*)d_in[0];
    const int*   rows = (const int*)  d_in[1];
    const int*   cols = (const int*)  d_in[2];
    const float* vals = (const float*)d_in[3];
    const float* W1   = (const float*)d_in[4];
    const float* G1   = (const float*)d_in[5];
    const float* W2   = (const float*)d_in[6];
    const float* G2   = (const float*)d_in[7];
    float* out = (float*)d_out;

    const int N = in_sizes[0] / D0;
    const int E = in_sizes[1];

    __nv_bfloat16 *Y1, *Y2, *Bt1, *Bt2;
    float *h, *evalp;
    int *counts, *rowptr, *cursor, *ecol, *bsum, *boff;
    cudaGetSymbolAddress((void**)&Y1,     g_Y1);
    cudaGetSymbolAddress((void**)&Y2,     g_Y2);
    cudaGetSymbolAddress((void**)&h,      g_h);
    cudaGetSymbolAddress((void**)&Bt1,    g_Bt1);
    cudaGetSymbolAddress((void**)&Bt2,    g_Bt2);
    cudaGetSymbolAddress((void**)&counts, g_counts);
    cudaGetSymbolAddress((void**)&rowptr, g_rowptr);
    cudaGetSymbolAddress((void**)&cursor, g_cursor);
    cudaGetSymbolAddress((void**)&ecol,   g_ecol);
    cudaGetSymbolAddress((void**)&evalp,  g_eval);
    cudaGetSymbolAddress((void**)&bsum,   g_bsum);
    cudaGetSymbolAddress((void**)&boff,   g_boff);

    cudaFuncSetAttribute(gemm_gate<true>,  cudaFuncAttributeMaxDynamicSharedMemorySize, SM_TOTAL);
    cudaFuncSetAttribute(gemm_gate<false>, cudaFuncAttributeMaxDynamicSharedMemorySize, SM_TOTAL);

    const int mtiles  = (N + 127) / 128;
    const int eblocks = (E + 255) / 256;
    const int nscan   = (N + SCAN_B - 1) / SCAN_B;

    // ---- weight prep + CSR build ----
    conv_w<<<(2 * D1 * 256 + 255) / 256, 256>>>(W1, G1, Bt1, D1);
    conv_w<<<(2 * D2 * 256 + 255) / 256, 256>>>(W2, G2, Bt2, D2);
    cudaMemsetAsync(counts, 0, (size_t)N * sizeof(int));
    hist_kernel<<<eblocks, 256>>>(rows, counts, E);
    scan_blocksum<<<nscan, SCAN_B>>>(counts, bsum, N);
    scan_offsets<<<1, 32>>>(bsum, boff, rowptr, nscan, N);
    scan_final<<<nscan, SCAN_B>>>(counts, boff, rowptr, cursor, N);
    scatter_kernel<<<eblocks, 256>>>(rows, cols, vals, cursor, ecol, evalp, E);

    // ---- layer 1: Y1 = A@x ; h = relu(sigmoid(Y1@G1) * (Y1@W1)) ----
    spmm_split<<<(N + 3) / 4, 256>>>(rowptr, ecol, evalp, x, Y1, N);
    gemm_gate<true><<<dim3(4, mtiles), 256, SM_TOTAL>>>(Y1, Bt1, h, N, D1);

    // ---- layer 2: Y2 = A@h ; out = sigmoid(Y2@G2) * (Y2@W2) ----
    spmm_split<<<(N + 3) / 4, 256>>>(rowptr, ecol, evalp, h, Y2, N);
    gemm_gate<false><<<dim3(2, mtiles), 256, SM_TOTAL>>>(Y2, Bt2, out, N, D2);
}

// round 9
// speedup vs baseline: 1.5994x; 1.0056x over previous
#include <cuda_runtime.h>
#include <cuda_bf16.h>
#include <cuda_fp16.h>
#include <math.h>
#include <stdint.h>

// ---------------------------------------------------------------------------
// GatedGCN on GB300 — round 7
//   Per layer: Y = A@feat (SpMM gather) then fused GEMM Y@[W|G] with
//   in-register sigmoid gating (W/G column-interleaved, split-bf16 3-term).
//   NEW vs round 6: features gathered in fp16 (x converted once; h written
//   fp16 by the layer-1 GEMM epilogue) -> SpMM gather traffic halved.
// ---------------------------------------------------------------------------

#define MAXN 50000
#define MAXE 800000
#define D0 256
#define D1 256
#define D2 128
#define SCAN_B 1024
#define MAXSB ((MAXN + SCAN_B - 1) / SCAN_B)

// ---------------- scratch (device globals) ----------------
__device__ __half         g_xh[(size_t)MAXN * 256];    // x in fp16
__device__ __half         g_h [(size_t)MAXN * 256];    // hidden in fp16
__device__ __nv_bfloat16 g_Y1[(size_t)MAXN * 512];     // [N,512] = [Y1h | Y1l]
__device__ __nv_bfloat16 g_Y2[(size_t)MAXN * 512];     // [N,512] = [Y2h | Y2l]
__device__ __nv_bfloat16 g_Bt1[(size_t)512 * 768];     // interleaved W1/G1 cols
__device__ __nv_bfloat16 g_Bt2[(size_t)256 * 768];     // interleaved W2/G2 cols
__device__ int   g_counts[MAXN];
__device__ int   g_rowptr[MAXN + 1];
__device__ int   g_cursor[MAXN];
__device__ int   g_ecol[MAXE];
__device__ float g_eval[MAXE];
__device__ int   g_bsum[MAXSB + 1];
__device__ int   g_boff[MAXSB + 1];

// ---------------- PTX helpers ----------------
__device__ __forceinline__ uint32_t smem_u32(const void* p) {
    uint32_t a;
    asm("{ .reg .u64 t; cvta.to.shared.u64 t, %1; cvt.u32.u64 %0, t; }" : "=r"(a) : "l"(p));
    return a;
}
__device__ __forceinline__ uint32_t swz(uint32_t o) { return o ^ ((o >> 3) & 0x70); }

__device__ __forceinline__ void cp16(uint32_t dst, const void* src, int sz) {
    asm volatile("cp.async.cg.shared.global [%0], [%1], 16, %2;"
                 :: "r"(dst), "l"(src), "r"(sz));
}
__device__ __forceinline__ void cp_commit() { asm volatile("cp.async.commit_group;"); }
__device__ __forceinline__ void cp_wait1()  { asm volatile("cp.async.wait_group 1;"); }

__device__ __forceinline__ void ldm_x4(uint32_t& r0, uint32_t& r1, uint32_t& r2, uint32_t& r3,
                                       uint32_t addr) {
    asm volatile("ldmatrix.sync.aligned.m8n8.x4.shared.b16 {%0,%1,%2,%3}, [%4];"
                 : "=r"(r0), "=r"(r1), "=r"(r2), "=r"(r3) : "r"(addr));
}
__device__ __forceinline__ void mma_bf16(float& d0, float& d1, float& d2, float& d3,
                                         uint32_t a0, uint32_t a1, uint32_t a2, uint32_t a3,
                                         uint32_t b0, uint32_t b1) {
    asm volatile("mma.sync.aligned.m16n8k16.row.col.f32.bf16.bf16.f32 "
                 "{%0,%1,%2,%3}, {%4,%5,%6,%7}, {%8,%9}, {%0,%1,%2,%3};"
                 : "+f"(d0), "+f"(d1), "+f"(d2), "+f"(d3)
                 : "r"(a0), "r"(a1), "r"(a2), "r"(a3), "r"(b0), "r"(b1));
}

__device__ __forceinline__ void split_bf16(float v, __nv_bfloat16& h, __nv_bfloat16& l) {
    h = __float2bfloat16(v);
    l = __float2bfloat16(v - __bfloat162float(h));
}
__device__ __forceinline__ float sigmoidf_(float x) { return 1.0f / (1.0f + __expf(-x)); }

// ---------------------------------------------------------------------------
// x [N,256] fp32 -> fp16
// ---------------------------------------------------------------------------
__global__ void conv_xh(const float* __restrict__ x, __half* __restrict__ xh, size_t total4)
{
    size_t idx = (size_t)blockIdx.x * blockDim.x + threadIdx.x;
    if (idx >= total4) return;
    float4 v = *reinterpret_cast<const float4*>(x + idx * 4);
    __half2 a = __floats2half2_rn(v.x, v.y);
    __half2 b = __floats2half2_rn(v.z, v.w);
    *reinterpret_cast<uint2*>(xh + idx * 4) =
        make_uint2(*reinterpret_cast<uint32_t*>(&a), *reinterpret_cast<uint32_t*>(&b));
}

// ---------------------------------------------------------------------------
// Weight prep: W,G [256,Nw] fp32 -> Bt [2Nw][768] bf16.
// Row n: n even -> W[:, n/2], n odd -> G[:, n/2].  K' = [hi | lo | hi].
// ---------------------------------------------------------------------------
__global__ void conv_w(const float* __restrict__ W, const float* __restrict__ G,
                       __nv_bfloat16* __restrict__ Bt, int Nw)
{
    int idx = blockIdx.x * blockDim.x + threadIdx.x;
    int twoNw = 2 * Nw;
    if (idx >= twoNw * 256) return;
    int n = idx % twoNw;
    int k = idx / twoNw;
    int j = n >> 1;
    float w = (n & 1) ? G[(size_t)k * Nw + j] : W[(size_t)k * Nw + j];
    __nv_bfloat16 h, l;
    split_bf16(w, h, l);
    __nv_bfloat16* row = Bt + (size_t)n * 768;
    row[k]       = h;
    row[256 + k] = l;
    row[512 + k] = h;
}

// ---------------------------------------------------------------------------
// CSR build
// ---------------------------------------------------------------------------
__global__ void hist_kernel(const int* __restrict__ rows, int* __restrict__ counts, int E)
{
    int i = blockIdx.x * blockDim.x + threadIdx.x;
    if (i < E) atomicAdd(&counts[rows[i]], 1);
}

__global__ __launch_bounds__(SCAN_B)
void scan_blocksum(const int* __restrict__ counts, int* __restrict__ bsum, int n)
{
    __shared__ int ws[32];
    const int tid  = threadIdx.x;
    const int lane = tid & 31;
    const int wid  = tid >> 5;
    int i = blockIdx.x * SCAN_B + tid;
    int v = (i < n) ? counts[i] : 0;
#pragma unroll
    for (int d = 16; d > 0; d >>= 1) v += __shfl_down_sync(0xffffffffu, v, d);
    if (lane == 0) ws[wid] = v;
    __syncthreads();
    if (wid == 0) {
        int w = ws[lane];
#pragma unroll
        for (int d = 16; d > 0; d >>= 1) w += __shfl_down_sync(0xffffffffu, w, d);
        if (lane == 0) bsum[blockIdx.x] = w;
    }
}

__global__ void scan_offsets(const int* __restrict__ bsum, int* __restrict__ boff,
                             int* __restrict__ rowptr, int nb, int n)
{
    if (threadIdx.x == 0) {
        int run = 0;
        for (int b = 0; b < nb; b++) { boff[b] = run; run += bsum[b]; }
        rowptr[n] = run;
    }
}

__global__ __launch_bounds__(SCAN_B)
void scan_final(const int* __restrict__ counts, const int* __restrict__ boff,
                int* __restrict__ rowptr, int* __restrict__ cursor, int n)
{
    __shared__ int ws[32];
    const int tid  = threadIdx.x;
    const int lane = tid & 31;
    const int wid  = tid >> 5;
    int i = blockIdx.x * SCAN_B + tid;
    int v = (i < n) ? counts[i] : 0;
    int x = v;
#pragma unroll
    for (int d = 1; d < 32; d <<= 1) {
        int y = __shfl_up_sync(0xffffffffu, x, d);
        if (lane >= d) x += y;
    }
    if (lane == 31) ws[wid] = x;
    __syncthreads();
    if (wid == 0) {
        int w = ws[lane];
#pragma unroll
        for (int d = 1; d < 32; d <<= 1) {
            int y = __shfl_up_sync(0xffffffffu, w, d);
            if (lane >= d) w += y;
        }
        ws[lane] = w;
    }
    __syncthreads();
    int excl = x - v + ((wid > 0) ? ws[wid - 1] : 0) + boff[blockIdx.x];
    if (i < n) { rowptr[i] = excl; cursor[i] = excl; }
}

__global__ void scatter_kernel(const int* __restrict__ rows, const int* __restrict__ cols,
                               const float* __restrict__ vals, int* __restrict__ cursor,
                               int* __restrict__ ecol, float* __restrict__ eval_, int E)
{
    int i = blockIdx.x * blockDim.x + threadIdx.x;
    if (i < E) {
        int pos = atomicAdd(&cursor[rows[i]], 1);
        ecol[pos]  = cols[i];
        eval_[pos] = vals[i];
    }
}

// ---------------------------------------------------------------------------
// SpMM: Y[r,:] = sum_e vals[e] * src[cols[e], :]  (src [N,256] fp16)
// 4 rows per 256-thread block (64 threads/row, 4 halves each), unroll-4.
// fp32 accumulate; epilogue writes bf16 hi/lo split [N,512].
// ---------------------------------------------------------------------------
__device__ __forceinline__ void acc_h4(float4& acc, float v, uint2 u)
{
    float2 f01 = __half22float2(*reinterpret_cast<__half2*>(&u.x));
    float2 f23 = __half22float2(*reinterpret_cast<__half2*>(&u.y));
    acc.x = fmaf(v, f01.x, acc.x); acc.y = fmaf(v, f01.y, acc.y);
    acc.z = fmaf(v, f23.x, acc.z); acc.w = fmaf(v, f23.y, acc.w);
}

__global__ __launch_bounds__(256)
void spmm_split(const int* __restrict__ rowptr,
                const int* __restrict__ ecol,
                const float* __restrict__ eval_,
                const __half* __restrict__ src,         // [N,256] fp16
                __nv_bfloat16* __restrict__ outs,       // [N,512] = [hi | lo]
                int N)
{
    const int g = threadIdx.x >> 6;                     // row group 0..3
    const int t = threadIdx.x & 63;                     // 4-half chunk idx
    const int r = blockIdx.x * 4 + g;
    if (r >= N) return;

    const int s = rowptr[r];
    const int e = rowptr[r + 1];

    const uint2* __restrict__ srcv = reinterpret_cast<const uint2*>(src);

    float4 acc = make_float4(0.f, 0.f, 0.f, 0.f);

    int i = s;
    for (; i + 3 < e; i += 4) {
        int   c0 = ecol[i];      int   c1 = ecol[i + 1];
        int   c2 = ecol[i + 2];  int   c3 = ecol[i + 3];
        float v0 = eval_[i];     float v1 = eval_[i + 1];
        float v2 = eval_[i + 2]; float v3 = eval_[i + 3];
        uint2 u0 = srcv[(size_t)c0 * 64 + t];
        uint2 u1 = srcv[(size_t)c1 * 64 + t];
        uint2 u2 = srcv[(size_t)c2 * 64 + t];
        uint2 u3 = srcv[(size_t)c3 * 64 + t];
        acc_h4(acc, v0, u0);
        acc_h4(acc, v1, u1);
        acc_h4(acc, v2, u2);
        acc_h4(acc, v3, u3);
    }
    for (; i < e; i++) {
        int   c = ecol[i];
        float v = eval_[i];
        acc_h4(acc, v, srcv[(size_t)c * 64 + t]);
    }

    float av[4] = {acc.x, acc.y, acc.z, acc.w};
    __nv_bfloat16 h[4], l[4];
#pragma unroll
    for (int j = 0; j < 4; j++) split_bf16(av[j], h[j], l[j]);
    __nv_bfloat16* base = outs + (size_t)r * 512 + t * 4;
    *reinterpret_cast<__nv_bfloat162*>(base)           = __halves2bfloat162(h[0], h[1]);
    *reinterpret_cast<__nv_bfloat162*>(base + 2)       = __halves2bfloat162(h[2], h[3]);
    *reinterpret_cast<__nv_bfloat162*>(base + 256)     = __halves2bfloat162(l[0], l[1]);
    *reinterpret_cast<__nv_bfloat162*>(base + 256 + 2) = __halves2bfloat162(l[2], l[3]);
}

// ---------------------------------------------------------------------------
// mma.sync GEMM with fused gating epilogue.
// HALF_OUT: gated output written as fp16 (hidden h); else fp32 (logits).
// ---------------------------------------------------------------------------
#define CH_BYTES 16384
#define SM_A0 0
#define SM_B0 (2 * CH_BYTES)
#define SM_TOTAL (4 * CH_BYTES)
#define NCHUNK 12

template <bool RELU, bool HALF_OUT>
__global__ __launch_bounds__(256)
void gemm_gate(const __nv_bfloat16* __restrict__ A2,   // [M, 512]
               const __nv_bfloat16* __restrict__ Bt,   // [2Nw, 768]
               void* __restrict__ Cg,                  // [M, OutW]
               int M, int OutW)
{
    extern __shared__ char smem[];
    const uint32_t sb = smem_u32(smem);
    const int tid  = threadIdx.x;
    const int wid  = tid >> 5;
    const int lane = tid & 31;
    const int wm   = wid & 3;
    const int wn   = wid >> 2;
    const int m0    = blockIdx.y * 128;
    const int nbase = blockIdx.x * 128;

    const char* Ab = (const char*)A2;
    const char* Bb = (const char*)Bt;

    auto load_chunk = [&](int kc, int st) {
        const uint32_t sA = sb + SM_A0 + st * CH_BYTES;
        const uint32_t sB = sb + SM_B0 + st * CH_BYTES;
        const int ak = (kc < 8) ? (kc & 3) : (kc - 4);  // Ah,Ah,Al sequence
        const size_t abyte = (size_t)ak * 128;
        const size_t bbyte = (size_t)kc * 128;
#pragma unroll
        for (int i = 0; i < 4; i++) {
            int g   = tid + i * 256;
            int row = g >> 3;
            int c   = (g & 7) * 16;
            int m   = m0 + row;
            int sz  = (m < M) ? 16 : 0;
            int mc  = (m < M) ? m : (M - 1);
            cp16(sA + swz((uint32_t)(row * 128 + c)),
                 Ab + (size_t)mc * 1024 + abyte + c, sz);
            cp16(sB + swz((uint32_t)(row * 128 + c)),
                 Bb + (size_t)(nbase + row) * 1536 + bbyte + c, 16);
        }
        cp_commit();
    };

    float acc[2][8][4];
#pragma unroll
    for (int i = 0; i < 2; i++)
#pragma unroll
        for (int j = 0; j < 8; j++)
#pragma unroll
            for (int q = 0; q < 4; q++) acc[i][j][q] = 0.f;

    load_chunk(0, 0);
    load_chunk(1, 1);

    const int a_row_in_tile = lane & 15;
    const int a_chunk_half  = lane >> 4;
    const int b_row_in_pair = lane & 7;
    const int b_chunk_half  = (lane >> 3) & 1;
    const int b_tile_sel    = lane >> 4;

    for (int kc = 0; kc < NCHUNK; kc++) {
        const int st = kc & 1;
        const uint32_t sA = sb + SM_A0 + st * CH_BYTES;
        const uint32_t sB = sb + SM_B0 + st * CH_BYTES;

        cp_wait1();
        __syncthreads();

#pragma unroll
        for (int ks = 0; ks < 4; ks++) {
            uint32_t a[2][4];
#pragma unroll
            for (int i = 0; i < 2; i++) {
                int row = wm * 32 + i * 16 + a_row_in_tile;
                uint32_t addr = sA + swz((uint32_t)(row * 128 + (ks * 2 + a_chunk_half) * 16));
                ldm_x4(a[i][0], a[i][1], a[i][2], a[i][3], addr);
            }
            uint32_t b[8][2];
#pragma unroll
            for (int jp = 0; jp < 4; jp++) {
                int row = wn * 64 + (jp * 2 + b_tile_sel) * 8 + b_row_in_pair;
                uint32_t addr = sB + swz((uint32_t)(row * 128 + (ks * 2 + b_chunk_half) * 16));
                uint32_t r0, r1, r2, r3;
                ldm_x4(r0, r1, r2, r3, addr);
                b[jp * 2 + 0][0] = r0; b[jp * 2 + 0][1] = r1;
                b[jp * 2 + 1][0] = r2; b[jp * 2 + 1][1] = r3;
            }
#pragma unroll
            for (int i = 0; i < 2; i++)
#pragma unroll
                for (int j = 0; j < 8; j++)
                    mma_bf16(acc[i][j][0], acc[i][j][1], acc[i][j][2], acc[i][j][3],
                             a[i][0], a[i][1], a[i][2], a[i][3],
                             b[j][0], b[j][1]);
        }

        __syncthreads();
        if (kc + 2 < NCHUNK) load_chunk(kc + 2, st);
        else cp_commit();
    }

    // ---- fused gating epilogue ----
    const int qrow = lane >> 2;
    const int qcol = (lane & 3) * 2;   // even -> (s, g) pair
#pragma unroll
    for (int i = 0; i < 2; i++) {
        int mA = m0 + wm * 32 + i * 16 + qrow;
        int mB = mA + 8;
#pragma unroll
        for (int j = 0; j < 8; j++) {
            int col = nbase + wn * 64 + j * 8 + qcol;
            int p   = col >> 1;
            float vA = sigmoidf_(acc[i][j][1]) * acc[i][j][0];
            float vB = sigmoidf_(acc[i][j][3]) * acc[i][j][2];
            if (RELU) { vA = fmaxf(vA, 0.f); vB = fmaxf(vB, 0.f); }
            if (HALF_OUT) {
                __half* C = (__half*)Cg;
                if (mA < M) C[(size_t)mA * OutW + p] = __float2half_rn(vA);
                if (mB < M) C[(size_t)mB * OutW + p] = __float2half_rn(vB);
            } else {
                float* C = (float*)Cg;
                if (mA < M) C[(size_t)mA * OutW + p] = vA;
                if (mB < M) C[(size_t)mB * OutW + p] = vB;
            }
        }
    }
}

// ---------------------------------------------------------------------------
// kernel_launch — inputs: x, rows, cols, vals, W1, G1, W2, G2
// ---------------------------------------------------------------------------
extern "C" void kernel_launch(void* const* d_in, const int* in_sizes, int n_in,
                              void* d_out, int out_size)
{
    const float* x    = (const float*)d_in[0];
    const int*   rows = (const int*)  d_in[1];
    const int*   cols = (const int*)  d_in[2];
    const float* vals = (const float*)d_in[3];
    const float* W1   = (const float*)d_in[4];
    const float* G1   = (const float*)d_in[5];
    const float* W2   = (const float*)d_in[6];
    const float* G2   = (const float*)d_in[7];
    float* out = (float*)d_out;

    const int N = in_sizes[0] / D0;
    const int E = in_sizes[1];

    __nv_bfloat16 *Y1, *Y2, *Bt1, *Bt2;
    __half *xh, *h;
    float *evalp;
    int *counts, *rowptr, *cursor, *ecol, *bsum, *boff;
    cudaGetSymbolAddress((void**)&xh,     g_xh);
    cudaGetSymbolAddress((void**)&h,      g_h);
    cudaGetSymbolAddress((void**)&Y1,     g_Y1);
    cudaGetSymbolAddress((void**)&Y2,     g_Y2);
    cudaGetSymbolAddress((void**)&Bt1,    g_Bt1);
    cudaGetSymbolAddress((void**)&Bt2,    g_Bt2);
    cudaGetSymbolAddress((void**)&counts, g_counts);
    cudaGetSymbolAddress((void**)&rowptr, g_rowptr);
    cudaGetSymbolAddress((void**)&cursor, g_cursor);
    cudaGetSymbolAddress((void**)&ecol,   g_ecol);
    cudaGetSymbolAddress((void**)&evalp,  g_eval);
    cudaGetSymbolAddress((void**)&bsum,   g_bsum);
    cudaGetSymbolAddress((void**)&boff,   g_boff);

    cudaFuncSetAttribute((const void*)gemm_gate<true, true>,
                         cudaFuncAttributeMaxDynamicSharedMemorySize, SM_TOTAL);
    cudaFuncSetAttribute((const void*)gemm_gate<false, false>,
                         cudaFuncAttributeMaxDynamicSharedMemorySize, SM_TOTAL);

    const int mtiles  = (N + 127) / 128;
    const int eblocks = (E + 255) / 256;
    const int nscan   = (N + SCAN_B - 1) / SCAN_B;

    // ---- operand prep + CSR build ----
    conv_xh<<<(int)(((size_t)N * 64 + 255) / 256), 256>>>(x, xh, (size_t)N * 64);
    conv_w<<<(2 * D1 * 256 + 255) / 256, 256>>>(W1, G1, Bt1, D1);
    conv_w<<<(2 * D2 * 256 + 255) / 256, 256>>>(W2, G2, Bt2, D2);
    cudaMemsetAsync(counts, 0, (size_t)N * sizeof(int));
    hist_kernel<<<eblocks, 256>>>(rows, counts, E);
    scan_blocksum<<<nscan, SCAN_B>>>(counts, bsum, N);
    scan_offsets<<<1, 32>>>(bsum, boff, rowptr, nscan, N);
    scan_final<<<nscan, SCAN_B>>>(counts, boff, rowptr, cursor, N);
    scatter_kernel<<<eblocks, 256>>>(rows, cols, vals, cursor, ecol, evalp, E);

    // ---- layer 1: Y1 = A@x ; h = relu(sigmoid(Y1@G1) * (Y1@W1)) (fp16) ----
    spmm_split<<<(N + 3) / 4, 256>>>(rowptr, ecol, evalp, xh, Y1, N);
    gemm_gate<true, true><<<dim3(4, mtiles), 256, SM_TOTAL>>>(Y1, Bt1, h, N, D1);

    // ---- layer 2: Y2 = A@h ; out = sigmoid(Y2@G2) * (Y2@W2) ----
    spmm_split<<<(N + 3) / 4, 256>>>(rowptr, ecol, evalp, h, Y2, N);
    gemm_gate<false, false><<<dim3(2, mtiles), 256, SM_TOTAL>>>(Y2, Bt2, out, N, D2);
}

// round 11
// speedup vs baseline: 1.6992x; 1.0624x over previous
#include <cuda_runtime.h>
#include <cuda_bf16.h>
#include <cuda_fp16.h>
#include <math.h>
#include <stdint.h>

// ---------------------------------------------------------------------------
// GatedGCN on GB300 — round 11
//   Round 10 retry: fixes the gather stride bug (row = 32 uint4, not 16).
//   Per layer: Y = A@feat (SpMM gather, fp16 features) then fused GEMM
//   Y@[W|G] with in-register sigmoid gating (split-bf16 3-term, K=768).
//   SpMM: 1 warp per row, LDG.128 per lane, unroll-8 edge loop.
// ---------------------------------------------------------------------------

#define MAXN 50000
#define MAXE 800000
#define D0 256
#define D1 256
#define D2 128
#define SCAN_B 1024
#define MAXSB ((MAXN + SCAN_B - 1) / SCAN_B)

// ---------------- scratch (device globals) ----------------
__device__ __half         g_xh[(size_t)MAXN * 256];    // x in fp16
__device__ __half         g_h [(size_t)MAXN * 256];    // hidden in fp16
__device__ __nv_bfloat16 g_Y1[(size_t)MAXN * 512];     // [N,512] = [Y1h | Y1l]
__device__ __nv_bfloat16 g_Y2[(size_t)MAXN * 512];     // [N,512] = [Y2h | Y2l]
__device__ __nv_bfloat16 g_Bt1[(size_t)512 * 768];     // interleaved W1/G1 cols
__device__ __nv_bfloat16 g_Bt2[(size_t)256 * 768];     // interleaved W2/G2 cols
__device__ int   g_counts[MAXN];
__device__ int   g_rowptr[MAXN + 1];
__device__ int   g_cursor[MAXN];
__device__ int   g_ecol[MAXE];
__device__ float g_eval[MAXE];
__device__ int   g_bsum[MAXSB + 1];
__device__ int   g_boff[MAXSB + 1];

// ---------------- PTX helpers ----------------
__device__ __forceinline__ uint32_t smem_u32(const void* p) {
    uint32_t a;
    asm("{ .reg .u64 t; cvta.to.shared.u64 t, %1; cvt.u32.u64 %0, t; }" : "=r"(a) : "l"(p));
    return a;
}
__device__ __forceinline__ uint32_t swz(uint32_t o) { return o ^ ((o >> 3) & 0x70); }

__device__ __forceinline__ void cp16(uint32_t dst, const void* src, int sz) {
    asm volatile("cp.async.cg.shared.global [%0], [%1], 16, %2;"
                 :: "r"(dst), "l"(src), "r"(sz));
}
__device__ __forceinline__ void cp_commit() { asm volatile("cp.async.commit_group;"); }
__device__ __forceinline__ void cp_wait1()  { asm volatile("cp.async.wait_group 1;"); }

__device__ __forceinline__ void ldm_x4(uint32_t& r0, uint32_t& r1, uint32_t& r2, uint32_t& r3,
                                       uint32_t addr) {
    asm volatile("ldmatrix.sync.aligned.m8n8.x4.shared.b16 {%0,%1,%2,%3}, [%4];"
                 : "=r"(r0), "=r"(r1), "=r"(r2), "=r"(r3) : "r"(addr));
}
__device__ __forceinline__ void mma_bf16(float& d0, float& d1, float& d2, float& d3,
                                         uint32_t a0, uint32_t a1, uint32_t a2, uint32_t a3,
                                         uint32_t b0, uint32_t b1) {
    asm volatile("mma.sync.aligned.m16n8k16.row.col.f32.bf16.bf16.f32 "
                 "{%0,%1,%2,%3}, {%4,%5,%6,%7}, {%8,%9}, {%0,%1,%2,%3};"
                 : "+f"(d0), "+f"(d1), "+f"(d2), "+f"(d3)
                 : "r"(a0), "r"(a1), "r"(a2), "r"(a3), "r"(b0), "r"(b1));
}

__device__ __forceinline__ void split_bf16(float v, __nv_bfloat16& h, __nv_bfloat16& l) {
    h = __float2bfloat16(v);
    l = __float2bfloat16(v - __bfloat162float(h));
}
__device__ __forceinline__ float sigmoidf_(float x) { return 1.0f / (1.0f + __expf(-x)); }

// ---------------------------------------------------------------------------
// x [N,256] fp32 -> fp16
// ---------------------------------------------------------------------------
__global__ void conv_xh(const float* __restrict__ x, __half* __restrict__ xh, size_t total4)
{
    size_t idx = (size_t)blockIdx.x * blockDim.x + threadIdx.x;
    if (idx >= total4) return;
    float4 v = *reinterpret_cast<const float4*>(x + idx * 4);
    __half2 a = __floats2half2_rn(v.x, v.y);
    __half2 b = __floats2half2_rn(v.z, v.w);
    *reinterpret_cast<uint2*>(xh + idx * 4) =
        make_uint2(*reinterpret_cast<uint32_t*>(&a), *reinterpret_cast<uint32_t*>(&b));
}

// ---------------------------------------------------------------------------
// Weight prep: W,G [256,Nw] fp32 -> Bt [2Nw][768] bf16.
// Row n: n even -> W[:, n/2], n odd -> G[:, n/2].  K' = [hi | lo | hi].
// ---------------------------------------------------------------------------
__global__ void conv_w(const float* __restrict__ W, const float* __restrict__ G,
                       __nv_bfloat16* __restrict__ Bt, int Nw)
{
    int idx = blockIdx.x * blockDim.x + threadIdx.x;
    int twoNw = 2 * Nw;
    if (idx >= twoNw * 256) return;
    int n = idx % twoNw;
    int k = idx / twoNw;
    int j = n >> 1;
    float w = (n & 1) ? G[(size_t)k * Nw + j] : W[(size_t)k * Nw + j];
    __nv_bfloat16 h, l;
    split_bf16(w, h, l);
    __nv_bfloat16* row = Bt + (size_t)n * 768;
    row[k]       = h;
    row[256 + k] = l;
    row[512 + k] = h;
}

// ---------------------------------------------------------------------------
// CSR build
// ---------------------------------------------------------------------------
__global__ void hist_kernel(const int* __restrict__ rows, int* __restrict__ counts, int E)
{
    int i = blockIdx.x * blockDim.x + threadIdx.x;
    if (i < E) atomicAdd(&counts[rows[i]], 1);
}

__global__ __launch_bounds__(SCAN_B)
void scan_blocksum(const int* __restrict__ counts, int* __restrict__ bsum, int n)
{
    __shared__ int ws[32];
    const int tid  = threadIdx.x;
    const int lane = tid & 31;
    const int wid  = tid >> 5;
    int i = blockIdx.x * SCAN_B + tid;
    int v = (i < n) ? counts[i] : 0;
#pragma unroll
    for (int d = 16; d > 0; d >>= 1) v += __shfl_down_sync(0xffffffffu, v, d);
    if (lane == 0) ws[wid] = v;
    __syncthreads();
    if (wid == 0) {
        int w = ws[lane];
#pragma unroll
        for (int d = 16; d > 0; d >>= 1) w += __shfl_down_sync(0xffffffffu, w, d);
        if (lane == 0) bsum[blockIdx.x] = w;
    }
}

__global__ void scan_offsets(const int* __restrict__ bsum, int* __restrict__ boff,
                             int* __restrict__ rowptr, int nb, int n)
{
    if (threadIdx.x == 0) {
        int run = 0;
        for (int b = 0; b < nb; b++) { boff[b] = run; run += bsum[b]; }
        rowptr[n] = run;
    }
}

__global__ __launch_bounds__(SCAN_B)
void scan_final(const int* __restrict__ counts, const int* __restrict__ boff,
                int* __restrict__ rowptr, int* __restrict__ cursor, int n)
{
    __shared__ int ws[32];
    const int tid  = threadIdx.x;
    const int lane = tid & 31;
    const int wid  = tid >> 5;
    int i = blockIdx.x * SCAN_B + tid;
    int v = (i < n) ? counts[i] : 0;
    int x = v;
#pragma unroll
    for (int d = 1; d < 32; d <<= 1) {
        int y = __shfl_up_sync(0xffffffffu, x, d);
        if (lane >= d) x += y;
    }
    if (lane == 31) ws[wid] = x;
    __syncthreads();
    if (wid == 0) {
        int w = ws[lane];
#pragma unroll
        for (int d = 1; d < 32; d <<= 1) {
            int y = __shfl_up_sync(0xffffffffu, w, d);
            if (lane >= d) w += y;
        }
        ws[lane] = w;
    }
    __syncthreads();
    int excl = x - v + ((wid > 0) ? ws[wid - 1] : 0) + boff[blockIdx.x];
    if (i < n) { rowptr[i] = excl; cursor[i] = excl; }
}

__global__ void scatter_kernel(const int* __restrict__ rows, const int* __restrict__ cols,
                               const float* __restrict__ vals, int* __restrict__ cursor,
                               int* __restrict__ ecol, float* __restrict__ eval_, int E)
{
    int i = blockIdx.x * blockDim.x + threadIdx.x;
    if (i < E) {
        int pos = atomicAdd(&cursor[rows[i]], 1);
        ecol[pos]  = cols[i];
        eval_[pos] = vals[i];
    }
}

// ---------------------------------------------------------------------------
// SpMM: Y[r,:] = sum_e vals[e] * src[cols[e], :]  (src [N,256] fp16)
// ONE WARP PER ROW. Lane owns 8 fp16 features = one uint4 (LDG.128).
// Row stride in uint4 units = 256/8 = 32.
// ---------------------------------------------------------------------------
__device__ __forceinline__ void acc_h8(float* acc, float v, uint4 u)
{
    const __half2* hp = reinterpret_cast<const __half2*>(&u);
#pragma unroll
    for (int q = 0; q < 4; q++) {
        float2 f = __half22float2(hp[q]);
        acc[q * 2 + 0] = fmaf(v, f.x, acc[q * 2 + 0]);
        acc[q * 2 + 1] = fmaf(v, f.y, acc[q * 2 + 1]);
    }
}

__global__ __launch_bounds__(256)
void spmm_split(const int* __restrict__ rowptr,
                const int* __restrict__ ecol,
                const float* __restrict__ eval_,
                const __half* __restrict__ src,         // [N,256] fp16
                __nv_bfloat16* __restrict__ outs,       // [N,512] = [hi | lo]
                int N)
{
    const int wid  = threadIdx.x >> 5;                  // warp in block: row
    const int lane = threadIdx.x & 31;                  // 8-feature chunk
    const int r = blockIdx.x * 8 + wid;
    if (r >= N) return;

    const int s = rowptr[r];
    const int e = rowptr[r + 1];

    const uint4* __restrict__ srcv = reinterpret_cast<const uint4*>(src);

    float acc[8];
#pragma unroll
    for (int q = 0; q < 8; q++) acc[q] = 0.f;

    int i = s;
    for (; i + 7 < e; i += 8) {
        int   c[8];
        float v[8];
#pragma unroll
        for (int j = 0; j < 8; j++) { c[j] = ecol[i + j]; v[j] = eval_[i + j]; }
        uint4 u[8];
#pragma unroll
        for (int j = 0; j < 8; j++) u[j] = srcv[(size_t)c[j] * 32 + lane];
#pragma unroll
        for (int j = 0; j < 8; j++) acc_h8(acc, v[j], u[j]);
    }
    for (; i < e; i++) {
        int   c = ecol[i];
        float v = eval_[i];
        acc_h8(acc, v, srcv[(size_t)c * 32 + lane]);
    }

    __nv_bfloat16 h[8], l[8];
#pragma unroll
    for (int q = 0; q < 8; q++) split_bf16(acc[q], h[q], l[q]);

    uint32_t hp[4], lp[4];
#pragma unroll
    for (int q = 0; q < 4; q++) {
        __nv_bfloat162 hh = __halves2bfloat162(h[q * 2], h[q * 2 + 1]);
        __nv_bfloat162 ll = __halves2bfloat162(l[q * 2], l[q * 2 + 1]);
        hp[q] = *reinterpret_cast<uint32_t*>(&hh);
        lp[q] = *reinterpret_cast<uint32_t*>(&ll);
    }
    __nv_bfloat16* base = outs + (size_t)r * 512 + lane * 8;
    *reinterpret_cast<uint4*>(base)       = make_uint4(hp[0], hp[1], hp[2], hp[3]);
    *reinterpret_cast<uint4*>(base + 256) = make_uint4(lp[0], lp[1], lp[2], lp[3]);
}

// ---------------------------------------------------------------------------
// mma.sync GEMM with fused gating epilogue.
// HALF_OUT: gated output written as fp16 (hidden h); else fp32 (logits).
// ---------------------------------------------------------------------------
#define CH_BYTES 16384
#define SM_A0 0
#define SM_B0 (2 * CH_BYTES)
#define SM_TOTAL (4 * CH_BYTES)
#define NCHUNK 12

template <bool RELU, bool HALF_OUT>
__global__ __launch_bounds__(256)
void gemm_gate(const __nv_bfloat16* __restrict__ A2,   // [M, 512]
               const __nv_bfloat16* __restrict__ Bt,   // [2Nw, 768]
               void* __restrict__ Cg,                  // [M, OutW]
               int M, int OutW)
{
    extern __shared__ char smem[];
    const uint32_t sb = smem_u32(smem);
    const int tid  = threadIdx.x;
    const int wid  = tid >> 5;
    const int lane = tid & 31;
    const int wm   = wid & 3;
    const int wn   = wid >> 2;
    const int m0    = blockIdx.y * 128;
    const int nbase = blockIdx.x * 128;

    const char* Ab = (const char*)A2;
    const char* Bb = (const char*)Bt;

    auto load_chunk = [&](int kc, int st) {
        const uint32_t sA = sb + SM_A0 + st * CH_BYTES;
        const uint32_t sB = sb + SM_B0 + st * CH_BYTES;
        const int ak = (kc < 8) ? (kc & 3) : (kc - 4);  // Ah,Ah,Al sequence
        const size_t abyte = (size_t)ak * 128;
        const size_t bbyte = (size_t)kc * 128;
#pragma unroll
        for (int i = 0; i < 4; i++) {
            int g   = tid + i * 256;
            int row = g >> 3;
            int c   = (g & 7) * 16;
            int m   = m0 + row;
            int sz  = (m < M) ? 16 : 0;
            int mc  = (m < M) ? m : (M - 1);
            cp16(sA + swz((uint32_t)(row * 128 + c)),
                 Ab + (size_t)mc * 1024 + abyte + c, sz);
            cp16(sB + swz((uint32_t)(row * 128 + c)),
                 Bb + (size_t)(nbase + row) * 1536 + bbyte + c, 16);
        }
        cp_commit();
    };

    float acc[2][8][4];
#pragma unroll
    for (int i = 0; i < 2; i++)
#pragma unroll
        for (int j = 0; j < 8; j++)
#pragma unroll
            for (int q = 0; q < 4; q++) acc[i][j][q] = 0.f;

    load_chunk(0, 0);
    load_chunk(1, 1);

    const int a_row_in_tile = lane & 15;
    const int a_chunk_half  = lane >> 4;
    const int b_row_in_pair = lane & 7;
    const int b_chunk_half  = (lane >> 3) & 1;
    const int b_tile_sel    = lane >> 4;

    for (int kc = 0; kc < NCHUNK; kc++) {
        const int st = kc & 1;
        const uint32_t sA = sb + SM_A0 + st * CH_BYTES;
        const uint32_t sB = sb + SM_B0 + st * CH_BYTES;

        cp_wait1();
        __syncthreads();

#pragma unroll
        for (int ks = 0; ks < 4; ks++) {
            uint32_t a[2][4];
#pragma unroll
            for (int i = 0; i < 2; i++) {
                int row = wm * 32 + i * 16 + a_row_in_tile;
                uint32_t addr = sA + swz((uint32_t)(row * 128 + (ks * 2 + a_chunk_half) * 16));
                ldm_x4(a[i][0], a[i][1], a[i][2], a[i][3], addr);
            }
            uint32_t b[8][2];
#pragma unroll
            for (int jp = 0; jp < 4; jp++) {
                int row = wn * 64 + (jp * 2 + b_tile_sel) * 8 + b_row_in_pair;
                uint32_t addr = sB + swz((uint32_t)(row * 128 + (ks * 2 + b_chunk_half) * 16));
                uint32_t r0, r1, r2, r3;
                ldm_x4(r0, r1, r2, r3, addr);
                b[jp * 2 + 0][0] = r0; b[jp * 2 + 0][1] = r1;
                b[jp * 2 + 1][0] = r2; b[jp * 2 + 1][1] = r3;
            }
#pragma unroll
            for (int i = 0; i < 2; i++)
#pragma unroll
                for (int j = 0; j < 8; j++)
                    mma_bf16(acc[i][j][0], acc[i][j][1], acc[i][j][2], acc[i][j][3],
                             a[i][0], a[i][1], a[i][2], a[i][3],
                             b[j][0], b[j][1]);
        }

        __syncthreads();
        if (kc + 2 < NCHUNK) load_chunk(kc + 2, st);
        else cp_commit();
    }

    // ---- fused gating epilogue ----
    const int qrow = lane >> 2;
    const int qcol = (lane & 3) * 2;   // even -> (s, g) pair
#pragma unroll
    for (int i = 0; i < 2; i++) {
        int mA = m0 + wm * 32 + i * 16 + qrow;
        int mB = mA + 8;
#pragma unroll
        for (int j = 0; j < 8; j++) {
            int col = nbase + wn * 64 + j * 8 + qcol;
            int p   = col >> 1;
            float vA = sigmoidf_(acc[i][j][1]) * acc[i][j][0];
            float vB = sigmoidf_(acc[i][j][3]) * acc[i][j][2];
            if (RELU) { vA = fmaxf(vA, 0.f); vB = fmaxf(vB, 0.f); }
            if (HALF_OUT) {
                __half* C = (__half*)Cg;
                if (mA < M) C[(size_t)mA * OutW + p] = __float2half_rn(vA);
                if (mB < M) C[(size_t)mB * OutW + p] = __float2half_rn(vB);
            } else {
                float* C = (float*)Cg;
                if (mA < M) C[(size_t)mA * OutW + p] = vA;
                if (mB < M) C[(size_t)mB * OutW + p] = vB;
            }
        }
    }
}

// ---------------------------------------------------------------------------
// kernel_launch — inputs: x, rows, cols, vals, W1, G1, W2, G2
// ---------------------------------------------------------------------------
extern "C" void kernel_launch(void* const* d_in, const int* in_sizes, int n_in,
                              void* d_out, int out_size)
{
    const float* x    = (const float*)d_in[0];
    const int*   rows = (const int*)  d_in[1];
    const int*   cols = (const int*)  d_in[2];
    const float* vals = (const float*)d_in[3];
    const float* W1   = (const float*)d_in[4];
    const float* G1   = (const float*)d_in[5];
    const float* W2   = (const float*)d_in[6];
    const float* G2   = (const float*)d_in[7];
    float* out = (float*)d_out;

    const int N = in_sizes[0] / D0;
    const int E = in_sizes[1];

    __nv_bfloat16 *Y1, *Y2, *Bt1, *Bt2;
    __half *xh, *h;
    float *evalp;
    int *counts, *rowptr, *cursor, *ecol, *bsum, *boff;
    cudaGetSymbolAddress((void**)&xh,     g_xh);
    cudaGetSymbolAddress((void**)&h,      g_h);
    cudaGetSymbolAddress((void**)&Y1,     g_Y1);
    cudaGetSymbolAddress((void**)&Y2,     g_Y2);
    cudaGetSymbolAddress((void**)&Bt1,    g_Bt1);
    cudaGetSymbolAddress((void**)&Bt2,    g_Bt2);
    cudaGetSymbolAddress((void**)&counts, g_counts);
    cudaGetSymbolAddress((void**)&rowptr, g_rowptr);
    cudaGetSymbolAddress((void**)&cursor, g_cursor);
    cudaGetSymbolAddress((void**)&ecol,   g_ecol);
    cudaGetSymbolAddress((void**)&evalp,  g_eval);
    cudaGetSymbolAddress((void**)&bsum,   g_bsum);
    cudaGetSymbolAddress((void**)&boff,   g_boff);

    cudaFuncSetAttribute((const void*)gemm_gate<true, true>,
                         cudaFuncAttributeMaxDynamicSharedMemorySize, SM_TOTAL);
    cudaFuncSetAttribute((const void*)gemm_gate<false, false>,
                         cudaFuncAttributeMaxDynamicSharedMemorySize, SM_TOTAL);

    const int mtiles  = (N + 127) / 128;
    const int eblocks = (E + 255) / 256;
    const int nscan   = (N + SCAN_B - 1) / SCAN_B;

    // ---- operand prep + CSR build ----
    conv_xh<<<(int)(((size_t)N * 64 + 255) / 256), 256>>>(x, xh, (size_t)N * 64);
    conv_w<<<(2 * D1 * 256 + 255) / 256, 256>>>(W1, G1, Bt1, D1);
    conv_w<<<(2 * D2 * 256 + 255) / 256, 256>>>(W2, G2, Bt2, D2);
    cudaMemsetAsync(counts, 0, (size_t)N * sizeof(int));
    hist_kernel<<<eblocks, 256>>>(rows, counts, E);
    scan_blocksum<<<nscan, SCAN_B>>>(counts, bsum, N);
    scan_offsets<<<1, 32>>>(bsum, boff, rowptr, nscan, N);
    scan_final<<<nscan, SCAN_B>>>(counts, boff, rowptr, cursor, N);
    scatter_kernel<<<eblocks, 256>>>(rows, cols, vals, cursor, ecol, evalp, E);

    // ---- layer 1: Y1 = A@x ; h = relu(sigmoid(Y1@G1) * (Y1@W1)) (fp16) ----
    spmm_split<<<(N + 7) / 8, 256>>>(rowptr, ecol, evalp, xh, Y1, N);
    gemm_gate<true, true><<<dim3(4, mtiles), 256, SM_TOTAL>>>(Y1, Bt1, h, N, D1);

    // ---- layer 2: Y2 = A@h ; out = sigmoid(Y2@G2) * (Y2@W2) ----
    spmm_split<<<(N + 7) / 8, 256>>>(rowptr, ecol, evalp, h, Y2, N);
    gemm_gate<false, false><<<dim3(2, mtiles), 256, SM_TOTAL>>>(Y2, Bt2, out, N, D2);
}

// round 12
// speedup vs baseline: 2.4980x; 1.4701x over previous
#include <cuda_runtime.h>
#include <cuda_bf16.h>
#include <cuda_fp16.h>
#include <math.h>
#include <stdint.h>

// ---------------------------------------------------------------------------
// GatedGCN on GB300 — round 12
//   Per layer: Y = A@feat (SpMM gather, fp16) then fused GEMM Y@[W|G] with
//   in-register sigmoid gating.
//   NEW vs round 11: GEMM is plain fp16 (K=256, single term) — features are
//   already fp16-quantized, so the split-bf16 3-term (K=768) precision was
//   wasted. GEMM traffic/MMAs drop 3x; SpMM epilogue writes fp16 Y directly
//   (half the output bytes, no hi/lo split).
// ---------------------------------------------------------------------------

#define MAXN 50000
#define MAXE 800000
#define D0 256
#define D1 256
#define D2 128
#define SCAN_B 1024
#define MAXSB ((MAXN + SCAN_B - 1) / SCAN_B)

// ---------------- scratch (device globals) ----------------
__device__ __half g_xh[(size_t)MAXN * 256];    // x in fp16
__device__ __half g_h [(size_t)MAXN * 256];    // hidden in fp16
__device__ __half g_Y1[(size_t)MAXN * 256];    // Y1 = A@x, fp16
__device__ __half g_Y2[(size_t)MAXN * 256];    // Y2 = A@h, fp16
__device__ __half g_Bt1[(size_t)512 * 256];    // interleaved W1/G1 cols, fp16, K-major rows
__device__ __half g_Bt2[(size_t)256 * 256];    // interleaved W2/G2 cols
__device__ int   g_counts[MAXN];
__device__ int   g_rowptr[MAXN + 1];
__device__ int   g_cursor[MAXN];
__device__ int   g_ecol[MAXE];
__device__ float g_eval[MAXE];
__device__ int   g_bsum[MAXSB + 1];
__device__ int   g_boff[MAXSB + 1];

// ---------------- PTX helpers ----------------
__device__ __forceinline__ uint32_t smem_u32(const void* p) {
    uint32_t a;
    asm("{ .reg .u64 t; cvta.to.shared.u64 t, %1; cvt.u32.u64 %0, t; }" : "=r"(a) : "l"(p));
    return a;
}
__device__ __forceinline__ uint32_t swz(uint32_t o) { return o ^ ((o >> 3) & 0x70); }

__device__ __forceinline__ void cp16(uint32_t dst, const void* src, int sz) {
    asm volatile("cp.async.cg.shared.global [%0], [%1], 16, %2;"
                 :: "r"(dst), "l"(src), "r"(sz));
}
__device__ __forceinline__ void cp_commit() { asm volatile("cp.async.commit_group;"); }
__device__ __forceinline__ void cp_wait1()  { asm volatile("cp.async.wait_group 1;"); }

__device__ __forceinline__ void ldm_x4(uint32_t& r0, uint32_t& r1, uint32_t& r2, uint32_t& r3,
                                       uint32_t addr) {
    asm volatile("ldmatrix.sync.aligned.m8n8.x4.shared.b16 {%0,%1,%2,%3}, [%4];"
                 : "=r"(r0), "=r"(r1), "=r"(r2), "=r"(r3) : "r"(addr));
}
__device__ __forceinline__ void mma_f16(float& d0, float& d1, float& d2, float& d3,
                                        uint32_t a0, uint32_t a1, uint32_t a2, uint32_t a3,
                                        uint32_t b0, uint32_t b1) {
    asm volatile("mma.sync.aligned.m16n8k16.row.col.f32.f16.f16.f32 "
                 "{%0,%1,%2,%3}, {%4,%5,%6,%7}, {%8,%9}, {%0,%1,%2,%3};"
                 : "+f"(d0), "+f"(d1), "+f"(d2), "+f"(d3)
                 : "r"(a0), "r"(a1), "r"(a2), "r"(a3), "r"(b0), "r"(b1));
}

__device__ __forceinline__ float sigmoidf_(float x) { return 1.0f / (1.0f + __expf(-x)); }

// ---------------------------------------------------------------------------
// x [N,256] fp32 -> fp16
// ---------------------------------------------------------------------------
__global__ void conv_xh(const float* __restrict__ x, __half* __restrict__ xh, size_t total4)
{
    size_t idx = (size_t)blockIdx.x * blockDim.x + threadIdx.x;
    if (idx >= total4) return;
    float4 v = *reinterpret_cast<const float4*>(x + idx * 4);
    __half2 a = __floats2half2_rn(v.x, v.y);
    __half2 b = __floats2half2_rn(v.z, v.w);
    *reinterpret_cast<uint2*>(xh + idx * 4) =
        make_uint2(*reinterpret_cast<uint32_t*>(&a), *reinterpret_cast<uint32_t*>(&b));
}

// ---------------------------------------------------------------------------
// Weight prep: W,G [256,Nw] fp32 -> Bt [2Nw][256] fp16.
// Row n: n even -> W[:, n/2], n odd -> G[:, n/2]  (column interleave).
// ---------------------------------------------------------------------------
__global__ void conv_w(const float* __restrict__ W, const float* __restrict__ G,
                       __half* __restrict__ Bt, int Nw)
{
    int idx = blockIdx.x * blockDim.x + threadIdx.x;
    int twoNw = 2 * Nw;
    if (idx >= twoNw * 256) return;
    int n = idx % twoNw;
    int k = idx / twoNw;
    int j = n >> 1;
    float w = (n & 1) ? G[(size_t)k * Nw + j] : W[(size_t)k * Nw + j];
    Bt[(size_t)n * 256 + k] = __float2half_rn(w);
}

// ---------------------------------------------------------------------------
// CSR build
// ---------------------------------------------------------------------------
__global__ void hist_kernel(const int* __restrict__ rows, int* __restrict__ counts, int E)
{
    int i = blockIdx.x * blockDim.x + threadIdx.x;
    if (i < E) atomicAdd(&counts[rows[i]], 1);
}

__global__ __launch_bounds__(SCAN_B)
void scan_blocksum(const int* __restrict__ counts, int* __restrict__ bsum, int n)
{
    __shared__ int ws[32];
    const int tid  = threadIdx.x;
    const int lane = tid & 31;
    const int wid  = tid >> 5;
    int i = blockIdx.x * SCAN_B + tid;
    int v = (i < n) ? counts[i] : 0;
#pragma unroll
    for (int d = 16; d > 0; d >>= 1) v += __shfl_down_sync(0xffffffffu, v, d);
    if (lane == 0) ws[wid] = v;
    __syncthreads();
    if (wid == 0) {
        int w = ws[lane];
#pragma unroll
        for (int d = 16; d > 0; d >>= 1) w += __shfl_down_sync(0xffffffffu, w, d);
        if (lane == 0) bsum[blockIdx.x] = w;
    }
}

__global__ void scan_offsets(const int* __restrict__ bsum, int* __restrict__ boff,
                             int* __restrict__ rowptr, int nb, int n)
{
    if (threadIdx.x == 0) {
        int run = 0;
        for (int b = 0; b < nb; b++) { boff[b] = run; run += bsum[b]; }
        rowptr[n] = run;
    }
}

__global__ __launch_bounds__(SCAN_B)
void scan_final(const int* __restrict__ counts, const int* __restrict__ boff,
                int* __restrict__ rowptr, int* __restrict__ cursor, int n)
{
    __shared__ int ws[32];
    const int tid  = threadIdx.x;
    const int lane = tid & 31;
    const int wid  = tid >> 5;
    int i = blockIdx.x * SCAN_B + tid;
    int v = (i < n) ? counts[i] : 0;
    int x = v;
#pragma unroll
    for (int d = 1; d < 32; d <<= 1) {
        int y = __shfl_up_sync(0xffffffffu, x, d);
        if (lane >= d) x += y;
    }
    if (lane == 31) ws[wid] = x;
    __syncthreads();
    if (wid == 0) {
        int w = ws[lane];
#pragma unroll
        for (int d = 1; d < 32; d <<= 1) {
            int y = __shfl_up_sync(0xffffffffu, w, d);
            if (lane >= d) w += y;
        }
        ws[lane] = w;
    }
    __syncthreads();
    int excl = x - v + ((wid > 0) ? ws[wid - 1] : 0) + boff[blockIdx.x];
    if (i < n) { rowptr[i] = excl; cursor[i] = excl; }
}

__global__ void scatter_kernel(const int* __restrict__ rows, const int* __restrict__ cols,
                               const float* __restrict__ vals, int* __restrict__ cursor,
                               int* __restrict__ ecol, float* __restrict__ eval_, int E)
{
    int i = blockIdx.x * blockDim.x + threadIdx.x;
    if (i < E) {
        int pos = atomicAdd(&cursor[rows[i]], 1);
        ecol[pos]  = cols[i];
        eval_[pos] = vals[i];
    }
}

// ---------------------------------------------------------------------------
// SpMM: Y[r,:] = sum_e vals[e] * src[cols[e], :]  (src [N,256] fp16)
// ONE WARP PER ROW. Lane owns 8 fp16 features = one uint4 (LDG.128).
// fp32 accumulate; epilogue writes fp16 [N,256].
// ---------------------------------------------------------------------------
__device__ __forceinline__ void acc_h8(float* acc, float v, uint4 u)
{
    const __half2* hp = reinterpret_cast<const __half2*>(&u);
#pragma unroll
    for (int q = 0; q < 4; q++) {
        float2 f = __half22float2(hp[q]);
        acc[q * 2 + 0] = fmaf(v, f.x, acc[q * 2 + 0]);
        acc[q * 2 + 1] = fmaf(v, f.y, acc[q * 2 + 1]);
    }
}

__global__ __launch_bounds__(256)
void spmm_f16(const int* __restrict__ rowptr,
              const int* __restrict__ ecol,
              const float* __restrict__ eval_,
              const __half* __restrict__ src,         // [N,256] fp16
              __half* __restrict__ outY,              // [N,256] fp16
              int N)
{
    const int wid  = threadIdx.x >> 5;                  // warp in block: row
    const int lane = threadIdx.x & 31;                  // 8-feature chunk
    const int r = blockIdx.x * 8 + wid;
    if (r >= N) return;

    const int s = rowptr[r];
    const int e = rowptr[r + 1];

    const uint4* __restrict__ srcv = reinterpret_cast<const uint4*>(src);

    float acc[8];
#pragma unroll
    for (int q = 0; q < 8; q++) acc[q] = 0.f;

    int i = s;
    for (; i + 7 < e; i += 8) {
        int   c[8];
        float v[8];
#pragma unroll
        for (int j = 0; j < 8; j++) { c[j] = ecol[i + j]; v[j] = eval_[i + j]; }
        uint4 u[8];
#pragma unroll
        for (int j = 0; j < 8; j++) u[j] = srcv[(size_t)c[j] * 32 + lane];
#pragma unroll
        for (int j = 0; j < 8; j++) acc_h8(acc, v[j], u[j]);
    }
    for (; i < e; i++) {
        int   c = ecol[i];
        float v = eval_[i];
        acc_h8(acc, v, srcv[(size_t)c * 32 + lane]);
    }

    uint32_t p[4];
#pragma unroll
    for (int q = 0; q < 4; q++) {
        __half2 hh = __floats2half2_rn(acc[q * 2], acc[q * 2 + 1]);
        p[q] = *reinterpret_cast<uint32_t*>(&hh);
    }
    *reinterpret_cast<uint4*>(outY + (size_t)r * 256 + lane * 8) =
        make_uint4(p[0], p[1], p[2], p[3]);
}

// ---------------------------------------------------------------------------
// fp16 mma.sync GEMM with fused gating epilogue.
//   A [M,256] fp16 (Y), Bt [2Nw,256] fp16 interleaved (K-major rows).
//   acc col pairs (even, odd) = (s_j, g_j); out = sigmoid(g)*s (+relu).
// 128x128 CTA tile, K-chunk 64 (4 chunks), double-buffered cp.async, SW128.
// HALF_OUT: output fp16 (hidden h); else fp32 (logits).
// ---------------------------------------------------------------------------
#define CH_BYTES 16384
#define SM_A0 0
#define SM_B0 (2 * CH_BYTES)
#define SM_TOTAL (4 * CH_BYTES)
#define NCHUNK 4

template <bool RELU, bool HALF_OUT>
__global__ __launch_bounds__(256)
void gemm_gate(const __half* __restrict__ A,           // [M, 256]
               const __half* __restrict__ Bt,          // [2Nw, 256]
               void* __restrict__ Cg,                  // [M, OutW]
               int M, int OutW)
{
    extern __shared__ char smem[];
    const uint32_t sb = smem_u32(smem);
    const int tid  = threadIdx.x;
    const int wid  = tid >> 5;
    const int lane = tid & 31;
    const int wm   = wid & 3;
    const int wn   = wid >> 2;
    const int m0    = blockIdx.y * 128;
    const int nbase = blockIdx.x * 128;

    const char* Ab = (const char*)A;
    const char* Bb = (const char*)Bt;

    auto load_chunk = [&](int kc, int st) {
        const uint32_t sA = sb + SM_A0 + st * CH_BYTES;
        const uint32_t sB = sb + SM_B0 + st * CH_BYTES;
        const size_t kbyte = (size_t)kc * 128;          // 64 fp16 = 128 B
#pragma unroll
        for (int i = 0; i < 4; i++) {
            int g   = tid + i * 256;
            int row = g >> 3;
            int c   = (g & 7) * 16;
            int m   = m0 + row;
            int sz  = (m < M) ? 16 : 0;
            int mc  = (m < M) ? m : (M - 1);
            cp16(sA + swz((uint32_t)(row * 128 + c)),
                 Ab + (size_t)mc * 512 + kbyte + c, sz);
            cp16(sB + swz((uint32_t)(row * 128 + c)),
                 Bb + (size_t)(nbase + row) * 512 + kbyte + c, 16);
        }
        cp_commit();
    };

    float acc[2][8][4];
#pragma unroll
    for (int i = 0; i < 2; i++)
#pragma unroll
        for (int j = 0; j < 8; j++)
#pragma unroll
            for (int q = 0; q < 4; q++) acc[i][j][q] = 0.f;

    load_chunk(0, 0);
    load_chunk(1, 1);

    const int a_row_in_tile = lane & 15;
    const int a_chunk_half  = lane >> 4;
    const int b_row_in_pair = lane & 7;
    const int b_chunk_half  = (lane >> 3) & 1;
    const int b_tile_sel    = lane >> 4;

    for (int kc = 0; kc < NCHUNK; kc++) {
        const int st = kc & 1;
        const uint32_t sA = sb + SM_A0 + st * CH_BYTES;
        const uint32_t sB = sb + SM_B0 + st * CH_BYTES;

        cp_wait1();
        __syncthreads();

#pragma unroll
        for (int ks = 0; ks < 4; ks++) {
            uint32_t a[2][4];
#pragma unroll
            for (int i = 0; i < 2; i++) {
                int row = wm * 32 + i * 16 + a_row_in_tile;
                uint32_t addr = sA + swz((uint32_t)(row * 128 + (ks * 2 + a_chunk_half) * 16));
                ldm_x4(a[i][0], a[i][1], a[i][2], a[i][3], addr);
            }
            uint32_t b[8][2];
#pragma unroll
            for (int jp = 0; jp < 4; jp++) {
                int row = wn * 64 + (jp * 2 + b_tile_sel) * 8 + b_row_in_pair;
                uint32_t addr = sB + swz((uint32_t)(row * 128 + (ks * 2 + b_chunk_half) * 16));
                uint32_t r0, r1, r2, r3;
                ldm_x4(r0, r1, r2, r3, addr);
                b[jp * 2 + 0][0] = r0; b[jp * 2 + 0][1] = r1;
                b[jp * 2 + 1][0] = r2; b[jp * 2 + 1][1] = r3;
            }
#pragma unroll
            for (int i = 0; i < 2; i++)
#pragma unroll
                for (int j = 0; j < 8; j++)
                    mma_f16(acc[i][j][0], acc[i][j][1], acc[i][j][2], acc[i][j][3],
                            a[i][0], a[i][1], a[i][2], a[i][3],
                            b[j][0], b[j][1]);
        }

        __syncthreads();
        if (kc + 2 < NCHUNK) load_chunk(kc + 2, st);
        else cp_commit();
    }

    // ---- fused gating epilogue ----
    const int qrow = lane >> 2;
    const int qcol = (lane & 3) * 2;   // even -> (s, g) pair
#pragma unroll
    for (int i = 0; i < 2; i++) {
        int mA = m0 + wm * 32 + i * 16 + qrow;
        int mB = mA + 8;
#pragma unroll
        for (int j = 0; j < 8; j++) {
            int col = nbase + wn * 64 + j * 8 + qcol;
            int p   = col >> 1;
            float vA = sigmoidf_(acc[i][j][1]) * acc[i][j][0];
            float vB = sigmoidf_(acc[i][j][3]) * acc[i][j][2];
            if (RELU) { vA = fmaxf(vA, 0.f); vB = fmaxf(vB, 0.f); }
            if (HALF_OUT) {
                __half* C = (__half*)Cg;
                if (mA < M) C[(size_t)mA * OutW + p] = __float2half_rn(vA);
                if (mB < M) C[(size_t)mB * OutW + p] = __float2half_rn(vB);
            } else {
                float* C = (float*)Cg;
                if (mA < M) C[(size_t)mA * OutW + p] = vA;
                if (mB < M) C[(size_t)mB * OutW + p] = vB;
            }
        }
    }
}

// ---------------------------------------------------------------------------
// kernel_launch — inputs: x, rows, cols, vals, W1, G1, W2, G2
// ---------------------------------------------------------------------------
extern "C" void kernel_launch(void* const* d_in, const int* in_sizes, int n_in,
                              void* d_out, int out_size)
{
    const float* x    = (const float*)d_in[0];
    const int*   rows = (const int*)  d_in[1];
    const int*   cols = (const int*)  d_in[2];
    const float* vals = (const float*)d_in[3];
    const float* W1   = (const float*)d_in[4];
    const float* G1   = (const float*)d_in[5];
    const float* W2   = (const float*)d_in[6];
    const float* G2   = (const float*)d_in[7];
    float* out = (float*)d_out;

    const int N = in_sizes[0] / D0;
    const int E = in_sizes[1];

    __half *xh, *h, *Y1, *Y2, *Bt1, *Bt2;
    float *evalp;
    int *counts, *rowptr, *cursor, *ecol, *bsum, *boff;
    cudaGetSymbolAddress((void**)&xh,     g_xh);
    cudaGetSymbolAddress((void**)&h,      g_h);
    cudaGetSymbolAddress((void**)&Y1,     g_Y1);
    cudaGetSymbolAddress((void**)&Y2,     g_Y2);
    cudaGetSymbolAddress((void**)&Bt1,    g_Bt1);
    cudaGetSymbolAddress((void**)&Bt2,    g_Bt2);
    cudaGetSymbolAddress((void**)&counts, g_counts);
    cudaGetSymbolAddress((void**)&rowptr, g_rowptr);
    cudaGetSymbolAddress((void**)&cursor, g_cursor);
    cudaGetSymbolAddress((void**)&ecol,   g_ecol);
    cudaGetSymbolAddress((void**)&evalp,  g_eval);
    cudaGetSymbolAddress((void**)&bsum,   g_bsum);
    cudaGetSymbolAddress((void**)&boff,   g_boff);

    cudaFuncSetAttribute((const void*)gemm_gate<true, true>,
                         cudaFuncAttributeMaxDynamicSharedMemorySize, SM_TOTAL);
    cudaFuncSetAttribute((const void*)gemm_gate<false, false>,
                         cudaFuncAttributeMaxDynamicSharedMemorySize, SM_TOTAL);

    const int mtiles  = (N + 127) / 128;
    const int eblocks = (E + 255) / 256;
    const int nscan   = (N + SCAN_B - 1) / SCAN_B;

    // ---- operand prep + CSR build ----
    conv_xh<<<(int)(((size_t)N * 64 + 255) / 256), 256>>>(x, xh, (size_t)N * 64);
    conv_w<<<(2 * D1 * 256 + 255) / 256, 256>>>(W1, G1, Bt1, D1);
    conv_w<<<(2 * D2 * 256 + 255) / 256, 256>>>(W2, G2, Bt2, D2);
    cudaMemsetAsync(counts, 0, (size_t)N * sizeof(int));
    hist_kernel<<<eblocks, 256>>>(rows, counts, E);
    scan_blocksum<<<nscan, SCAN_B>>>(counts, bsum, N);
    scan_offsets<<<1, 32>>>(bsum, boff, rowptr, nscan, N);
    scan_final<<<nscan, SCAN_B>>>(counts, boff, rowptr, cursor, N);
    scatter_kernel<<<eblocks, 256>>>(rows, cols, vals, cursor, ecol, evalp, E);

    // ---- layer 1: Y1 = A@x ; h = relu(sigmoid(Y1@G1) * (Y1@W1)) (fp16) ----
    spmm_f16<<<(N + 7) / 8, 256>>>(rowptr, ecol, evalp, xh, Y1, N);
    gemm_gate<true, true><<<dim3(4, mtiles), 256, SM_TOTAL>>>(Y1, Bt1, h, N, D1);

    // ---- layer 2: Y2 = A@h ; out = sigmoid(Y2@G2) * (Y2@W2) ----
    spmm_f16<<<(N + 7) / 8, 256>>>(rowptr, ecol, evalp, h, Y2, N);
    gemm_gate<false, false><<<dim3(2, mtiles), 256, SM_TOTAL>>>(Y2, Bt2, out, N, D2);
}